// round 2
// baseline (speedup 1.0000x reference)
#include <cuda_runtime.h>
#include <math.h>

#define Bz 512
#define Tz 128
#define Vz 64
#define Ez 256
#define Hz 512
#define Lz 128
#define G4z 2048
#define ELz 384

// ---------------- scratch (static device globals; no allocation) ----------------
// All sizes are multiples of 16B; force 16B alignment so float4 access is legal.
__device__ __align__(16) float g_P[(size_t)Tz * Bz * G4z];     // per-step input projections (reused 3x)
__device__ __align__(16) float g_h[2][Bz * Hz];                // double-buffered hidden state
__device__ __align__(16) float g_c[Bz * Hz];                   // cell state
__device__ __align__(16) float g_hcat[Bz * 2 * Hz];            // [hF, hB]
__device__ __align__(16) float g_z[Bz * Lz];                   // latent sample
__device__ __align__(16) float g_zp[Bz * G4z];                 // z @ Wih_d[:,E:]^T (time-invariant)
__device__ __align__(16) float g_hs[(size_t)Tz * Bz * Hz];     // decoder hidden states

__device__ __forceinline__ float sigm(float x) { return 1.0f / (1.0f + expf(-x)); }

// ---------------- zero h (both buffers) and c ----------------
__global__ void k_zero_state() {
    int i = blockIdx.x * blockDim.x + threadIdx.x;
    if (i < Bz * Hz) { g_h[0][i] = 0.0f; g_h[1][i] = 0.0f; g_c[i] = 0.0f; }
}

// ---------------- copy final hidden into hcat half ----------------
__global__ void k_copy_half(int off) {
    int i = blockIdx.x * blockDim.x + threadIdx.x;
    if (i < Bz * Hz) {
        int b = i >> 9;          // /Hz
        int j = i & (Hz - 1);
        g_hcat[b * (2 * Hz) + off + j] = g_h[0][i];
    }
}

// ---------------- reparameterize: z = mu + eps * exp(0.5*logvar) ----------------
__global__ void k_reparam(const float* __restrict__ eps,
                          const float* __restrict__ muv,
                          const float* __restrict__ lvv) {
    int i = blockIdx.x * blockDim.x + threadIdx.x;
    if (i < Bz * Lz) g_z[i] = muv[i] + eps[i] * expf(0.5f * lvv[i]);
}

// ---------------- P[t*B+b, n] = emb[tok(b,t)] @ W[n,:Ez]^T + bias[n] ----------------
// M = T*B (row = t*B+b), N = 2048, K = 256. 64x64 tile, BK=16, 256 threads, 4x4 micro.
// NOTE: token ids are int32 (JAX x64 disabled downcasts the requested int64).
__global__ __launch_bounds__(256) void k_proj(const int* __restrict__ ids, int rev,
                                              const float* __restrict__ emb,
                                              const float* __restrict__ W, int ldw,
                                              const float* __restrict__ bias) {
    __shared__ float As[16][68];
    __shared__ float Bs[16][68];
    __shared__ int toks[64];
    const int tid = threadIdx.x;
    const int m0 = blockIdx.y * 64;
    const int n0 = blockIdx.x * 64;
    if (tid < 64) {
        int m = m0 + tid;
        int b = m & (Bz - 1);
        int t = m >> 9;
        int tt = rev ? (Tz - 1 - t) : t;
        toks[tid] = ids[b * Tz + tt];
    }
    __syncthreads();
    const int lr = tid >> 2, lk = tid & 3;
    const int tx = tid & 15, ty = tid >> 4;
    float acc[4][4] = {};
    for (int k0 = 0; k0 < Ez; k0 += 16) {
        float4 av = *(const float4*)(emb + (size_t)toks[lr] * Ez + k0 + lk * 4);
        float4 bv = *(const float4*)(W + (size_t)(n0 + lr) * ldw + k0 + lk * 4);
        __syncthreads();
        As[lk*4+0][lr] = av.x; As[lk*4+1][lr] = av.y; As[lk*4+2][lr] = av.z; As[lk*4+3][lr] = av.w;
        Bs[lk*4+0][lr] = bv.x; Bs[lk*4+1][lr] = bv.y; Bs[lk*4+2][lr] = bv.z; Bs[lk*4+3][lr] = bv.w;
        __syncthreads();
#pragma unroll
        for (int k = 0; k < 16; k++) {
            float4 a = *(const float4*)&As[k][ty * 4];
            float4 b = *(const float4*)&Bs[k][tx * 4];
            acc[0][0] += a.x*b.x; acc[0][1] += a.x*b.y; acc[0][2] += a.x*b.z; acc[0][3] += a.x*b.w;
            acc[1][0] += a.y*b.x; acc[1][1] += a.y*b.y; acc[1][2] += a.y*b.z; acc[1][3] += a.y*b.w;
            acc[2][0] += a.z*b.x; acc[2][1] += a.z*b.y; acc[2][2] += a.z*b.z; acc[2][3] += a.z*b.w;
            acc[3][0] += a.w*b.x; acc[3][1] += a.w*b.y; acc[3][2] += a.w*b.z; acc[3][3] += a.w*b.w;
        }
    }
#pragma unroll
    for (int i = 0; i < 4; i++) {
        size_t row = (size_t)(m0 + ty * 4 + i) * G4z;
#pragma unroll
        for (int j = 0; j < 4; j++) {
            int n = n0 + tx * 4 + j;
            g_P[row + n] = acc[i][j] + bias[n];
        }
    }
}

// ---------------- generic small GEMM: C[M,N] = A[M,K] @ Bw[N,K]^T (+bias) ----------------
// a_sel: 0=Aext, 1=g_hcat, 2=g_z ; c_sel: 0=Cext, 1=g_zp, 2=g_h[0]
__global__ __launch_bounds__(256) void k_gemm(int K,
                                              const float* __restrict__ Aext, int lda,
                                              const float* __restrict__ Bw, int ldb,
                                              const float* __restrict__ bias,
                                              float* __restrict__ Cext, int ldc,
                                              int a_sel, int c_sel) {
    const float* A = (a_sel == 1) ? g_hcat : (a_sel == 2) ? g_z : Aext;
    float* C = (c_sel == 1) ? g_zp : (c_sel == 2) ? g_h[0] : Cext;
    __shared__ float As[16][68];
    __shared__ float Bs[16][68];
    const int tid = threadIdx.x;
    const int m0 = blockIdx.y * 64;
    const int n0 = blockIdx.x * 64;
    const int lr = tid >> 2, lk = tid & 3;
    const int tx = tid & 15, ty = tid >> 4;
    float acc[4][4] = {};
    for (int k0 = 0; k0 < K; k0 += 16) {
        float4 av = *(const float4*)(A + (size_t)(m0 + lr) * lda + k0 + lk * 4);
        float4 bv = *(const float4*)(Bw + (size_t)(n0 + lr) * ldb + k0 + lk * 4);
        __syncthreads();
        As[lk*4+0][lr] = av.x; As[lk*4+1][lr] = av.y; As[lk*4+2][lr] = av.z; As[lk*4+3][lr] = av.w;
        Bs[lk*4+0][lr] = bv.x; Bs[lk*4+1][lr] = bv.y; Bs[lk*4+2][lr] = bv.z; Bs[lk*4+3][lr] = bv.w;
        __syncthreads();
#pragma unroll
        for (int k = 0; k < 16; k++) {
            float4 a = *(const float4*)&As[k][ty * 4];
            float4 b = *(const float4*)&Bs[k][tx * 4];
            acc[0][0] += a.x*b.x; acc[0][1] += a.x*b.y; acc[0][2] += a.x*b.z; acc[0][3] += a.x*b.w;
            acc[1][0] += a.y*b.x; acc[1][1] += a.y*b.y; acc[1][2] += a.y*b.z; acc[1][3] += a.y*b.w;
            acc[2][0] += a.z*b.x; acc[2][1] += a.z*b.y; acc[2][2] += a.z*b.z; acc[2][3] += a.z*b.w;
            acc[3][0] += a.w*b.x; acc[3][1] += a.w*b.y; acc[3][2] += a.w*b.z; acc[3][3] += a.w*b.w;
        }
    }
#pragma unroll
    for (int i = 0; i < 4; i++)
#pragma unroll
        for (int j = 0; j < 4; j++) {
            int n = n0 + tx * 4 + j;
            float bb = bias ? bias[n] : 0.0f;
            C[(size_t)(m0 + ty * 4 + i) * ldc + n] = acc[i][j] + bb;
        }
}

// ---------------- fused LSTM timestep: g = h@Whh^T + P[t] (+zp); gates; update h,c ----------
// Block tile: 32 batch x 32 hidden-j (x 4 gates = 128 gate cols), K=512. 128 threads.
// Thread: 4 batch x 2 j x 4 gates = 32 accumulators.
__global__ __launch_bounds__(128) void k_step(int t, int pin,
                                              const float* __restrict__ Whh,
                                              int use_zp, int store_hs) {
    __shared__ float As[16][36];
    __shared__ float Ws[16][132];
    const int tid = threadIdx.x;
    const int j0 = blockIdx.x * 32;
    const int b0 = blockIdx.y * 32;
    const float* hin = g_h[pin];
    float* hout = g_h[pin ^ 1];
    const int lr = tid >> 2, lk = tid & 3;
    const int tx = tid & 15, ty = tid >> 4;
    float acc[4][4][2] = {};
    for (int k0 = 0; k0 < Hz; k0 += 16) {
        float4 av = *(const float4*)(hin + (size_t)(b0 + lr) * Hz + k0 + lk * 4);
        float4 wv[4];
#pragma unroll
        for (int r = 0; r < 4; r++) {
            int wr = lr + r * 32;                       // n_local = q*32 + j_local
            int row = (wr >> 5) * Hz + j0 + (wr & 31);  // global gate row q*H + j
            wv[r] = *(const float4*)(Whh + (size_t)row * Hz + k0 + lk * 4);
        }
        __syncthreads();
        As[lk*4+0][lr] = av.x; As[lk*4+1][lr] = av.y; As[lk*4+2][lr] = av.z; As[lk*4+3][lr] = av.w;
#pragma unroll
        for (int r = 0; r < 4; r++) {
            int wr = lr + r * 32;
            Ws[lk*4+0][wr] = wv[r].x; Ws[lk*4+1][wr] = wv[r].y;
            Ws[lk*4+2][wr] = wv[r].z; Ws[lk*4+3][wr] = wv[r].w;
        }
        __syncthreads();
#pragma unroll
        for (int k = 0; k < 16; k++) {
            float4 a = *(const float4*)&As[k][ty * 4];
            float av4[4] = {a.x, a.y, a.z, a.w};
#pragma unroll
            for (int q = 0; q < 4; q++) {
                float2 w = *(const float2*)&Ws[k][q * 32 + tx * 2];
#pragma unroll
                for (int i = 0; i < 4; i++) {
                    acc[i][q][0] += av4[i] * w.x;
                    acc[i][q][1] += av4[i] * w.y;
                }
            }
        }
    }
    // epilogue: add P (and zp), apply gates, update state
#pragma unroll
    for (int i = 0; i < 4; i++) {
        int b = b0 + ty * 4 + i;
        size_t prow = ((size_t)t * Bz + b) * G4z;
#pragma unroll
        for (int jj = 0; jj < 2; jj++) {
            int j = j0 + tx * 2 + jj;
            float gi = acc[i][0][jj] + g_P[prow + j];
            float gf = acc[i][1][jj] + g_P[prow + Hz + j];
            float gg = acc[i][2][jj] + g_P[prow + 2 * Hz + j];
            float go = acc[i][3][jj] + g_P[prow + 3 * Hz + j];
            if (use_zp) {
                const float* zp = g_zp + (size_t)b * G4z;
                gi += zp[j]; gf += zp[Hz + j]; gg += zp[2 * Hz + j]; go += zp[3 * Hz + j];
            }
            int idx = b * Hz + j;
            float cn = sigm(gf) * g_c[idx] + sigm(gi) * tanhf(gg);
            float hn = sigm(go) * tanhf(cn);
            g_c[idx] = cn;
            hout[idx] = hn;
            if (store_hs) g_hs[((size_t)t * Bz + b) * Hz + j] = hn;
        }
    }
}

// ---------------- output head: out[b,t,v] = hs[t,b,:] @ W_out[v,:]^T + b_out[v] ----------
__global__ __launch_bounds__(256) void k_outhead(const float* __restrict__ Wout,
                                                 const float* __restrict__ bout,
                                                 float* __restrict__ out) {
    __shared__ float As[16][68];
    __shared__ float Bs[16][68];
    const int tid = threadIdx.x;
    const int b0 = blockIdx.x * 64;
    const int t = blockIdx.y;
    const int lr = tid >> 2, lk = tid & 3;
    const int tx = tid & 15, ty = tid >> 4;
    float acc[4][4] = {};
    const float* hsrc = g_hs + (size_t)t * Bz * Hz;
    for (int k0 = 0; k0 < Hz; k0 += 16) {
        float4 av = *(const float4*)(hsrc + (size_t)(b0 + lr) * Hz + k0 + lk * 4);
        float4 bv = *(const float4*)(Wout + (size_t)lr * Hz + k0 + lk * 4);  // V=64 rows exactly
        __syncthreads();
        As[lk*4+0][lr] = av.x; As[lk*4+1][lr] = av.y; As[lk*4+2][lr] = av.z; As[lk*4+3][lr] = av.w;
        Bs[lk*4+0][lr] = bv.x; Bs[lk*4+1][lr] = bv.y; Bs[lk*4+2][lr] = bv.z; Bs[lk*4+3][lr] = bv.w;
        __syncthreads();
#pragma unroll
        for (int k = 0; k < 16; k++) {
            float4 a = *(const float4*)&As[k][ty * 4];
            float4 b = *(const float4*)&Bs[k][tx * 4];
            acc[0][0] += a.x*b.x; acc[0][1] += a.x*b.y; acc[0][2] += a.x*b.z; acc[0][3] += a.x*b.w;
            acc[1][0] += a.y*b.x; acc[1][1] += a.y*b.y; acc[1][2] += a.y*b.z; acc[1][3] += a.y*b.w;
            acc[2][0] += a.z*b.x; acc[2][1] += a.z*b.y; acc[2][2] += a.z*b.z; acc[2][3] += a.z*b.w;
            acc[3][0] += a.w*b.x; acc[3][1] += a.w*b.y; acc[3][2] += a.w*b.z; acc[3][3] += a.w*b.w;
        }
    }
#pragma unroll
    for (int i = 0; i < 4; i++) {
        int b = b0 + ty * 4 + i;
#pragma unroll
        for (int j = 0; j < 4; j++) {
            int v = tx * 4 + j;
            out[((size_t)b * Tz + t) * Vz + v] = acc[i][j] + bout[v];
        }
    }
}

// ---------------- launch ----------------
extern "C" void kernel_launch(void* const* d_in, const int* in_sizes, int n_in,
                              void* d_out, int out_size) {
    const int* x    = (const int*)d_in[0];   // int32 (JAX x64 disabled)
    const int* tgt  = (const int*)d_in[1];   // int32
    const float* eps  = (const float*)d_in[2];
    const float* emb  = (const float*)d_in[3];
    const float* Wih_f = (const float*)d_in[4];
    const float* Whh_f = (const float*)d_in[5];
    const float* b_f   = (const float*)d_in[6];
    const float* Wih_b = (const float*)d_in[7];
    const float* Whh_b = (const float*)d_in[8];
    const float* b_b   = (const float*)d_in[9];
    const float* W_mu  = (const float*)d_in[10];
    const float* b_mu  = (const float*)d_in[11];
    const float* W_lv  = (const float*)d_in[12];
    const float* b_lv  = (const float*)d_in[13];
    const float* W_di  = (const float*)d_in[14];
    const float* b_di  = (const float*)d_in[15];
    const float* Wih_d = (const float*)d_in[16];
    const float* Whh_d = (const float*)d_in[17];
    const float* b_d   = (const float*)d_in[18];
    const float* W_out = (const float*)d_in[19];
    const float* b_out = (const float*)d_in[20];

    float* out  = (float*)d_out;
    float* mu_o = out + (size_t)Bz * Tz * Vz;
    float* lv_o = mu_o + Bz * Lz;

    dim3 projGrid(G4z / 64, (Tz * Bz) / 64);
    dim3 stepGrid(Hz / 32, Bz / 32);
    int zeroBlocks = (Bz * Hz + 255) / 256;

    // ---- encoder forward ----
    k_proj<<<projGrid, 256>>>(x, 0, emb, Wih_f, Ez, b_f);
    k_zero_state<<<zeroBlocks, 256>>>();
    for (int t = 0; t < Tz; t++) k_step<<<stepGrid, 128>>>(t, t & 1, Whh_f, 0, 0);
    k_copy_half<<<zeroBlocks, 256>>>(0);

    // ---- encoder backward ----
    k_proj<<<projGrid, 256>>>(x, 1, emb, Wih_b, Ez, b_b);
    k_zero_state<<<zeroBlocks, 256>>>();
    for (int t = 0; t < Tz; t++) k_step<<<stepGrid, 128>>>(t, t & 1, Whh_b, 0, 0);
    k_copy_half<<<zeroBlocks, 256>>>(Hz);

    // ---- latent heads + reparameterize ----
    k_gemm<<<dim3(Lz / 64, Bz / 64), 256>>>(2 * Hz, nullptr, 2 * Hz, W_mu, 2 * Hz, b_mu, mu_o, Lz, 1, 0);
    k_gemm<<<dim3(Lz / 64, Bz / 64), 256>>>(2 * Hz, nullptr, 2 * Hz, W_lv, 2 * Hz, b_lv, lv_o, Lz, 1, 0);
    k_reparam<<<(Bz * Lz + 255) / 256, 256>>>(eps, mu_o, lv_o);

    // ---- decoder prologue ----
    k_gemm<<<dim3(G4z / 64, Bz / 64), 256>>>(Lz, nullptr, Lz, Wih_d + Ez, ELz, nullptr, nullptr, G4z, 2, 1); // g_zp
    k_proj<<<projGrid, 256>>>(tgt, 0, emb, Wih_d, ELz, b_d);
    k_zero_state<<<zeroBlocks, 256>>>();
    k_gemm<<<dim3(Hz / 64, Bz / 64), 256>>>(Lz, nullptr, Lz, W_di, Lz, b_di, nullptr, Hz, 2, 2);            // h0 = hd

    // ---- decoder recurrence ----
    for (int t = 0; t < Tz; t++) k_step<<<stepGrid, 128>>>(t, t & 1, Whh_d, 1, 1);

    // ---- output head ----
    k_outhead<<<dim3(Bz / 64, Tz), 256>>>(W_out, b_out, out);
}

// round 4
// speedup vs baseline: 2.4453x; 2.4453x over previous
#include <cuda_runtime.h>
#include <cuda_fp16.h>
#include <math.h>

#define Bz 512
#define Tz 128
#define Vz 64
#define Ez 256
#define Hz 512
#define Lz 128
#define G4z 2048
#define ELz 384
#define LDA 72
#define LDB 72

// ---------------- scratch (static device globals; no allocation) ----------------
__device__ __align__(16) float  g_P[(size_t)Tz * Bz * G4z];
__device__ __align__(16) __half g_h1[2][Bz * Hz];
__device__ __align__(16) __half g_h2[2][Bz * Hz];
__device__ __align__(16) float  g_c[Bz * Hz];
__device__ __align__(16) float  g_htmp[Bz * Hz];
__device__ __align__(16) float  g_hcat[Bz * 2 * Hz];
__device__ __align__(16) float  g_z[Bz * Lz];
__device__ __align__(16) float  g_zp[Bz * G4z];
__device__ __align__(16) __half g_hs1[(size_t)Tz * Bz * Hz];
__device__ __align__(16) __half g_hs2[(size_t)Tz * Bz * Hz];
// split-fp16 weight copies (X = X1 + X2, X2 = fp16(X - fp16(X)))
__device__ __align__(16) __half g_e1[Vz * Ez],    g_e2[Vz * Ez];
__device__ __align__(16) __half g_Wf1[G4z * Ez],  g_Wf2[G4z * Ez];
__device__ __align__(16) __half g_Wb1[G4z * Ez],  g_Wb2[G4z * Ez];
__device__ __align__(16) __half g_Wd1[G4z * ELz], g_Wd2[G4z * ELz];
__device__ __align__(16) __half g_Uf1[G4z * Hz],  g_Uf2[G4z * Hz];
__device__ __align__(16) __half g_Ub1[G4z * Hz],  g_Ub2[G4z * Hz];
__device__ __align__(16) __half g_Ud1[G4z * Hz],  g_Ud2[G4z * Hz];
__device__ __align__(16) __half g_Wo1[Vz * Hz],   g_Wo2[Vz * Hz];

__device__ __forceinline__ float sigm(float x) { return 1.0f / (1.0f + expf(-x)); }

__device__ __forceinline__ void mma16816(float* d, const unsigned* a, unsigned b0, unsigned b1) {
    asm volatile("mma.sync.aligned.m16n8k16.row.col.f32.f16.f16.f32 "
                 "{%0,%1,%2,%3},{%4,%5,%6,%7},{%8,%9},{%0,%1,%2,%3};"
                 : "+f"(d[0]), "+f"(d[1]), "+f"(d[2]), "+f"(d[3])
                 : "r"(a[0]), "r"(a[1]), "r"(a[2]), "r"(a[3]), "r"(b0), "r"(b1));
}

#define SMEM_STEP ((2*64*LDA + 2*128*LDB) * 2)   // 55296 B
#define SMEM_OUT  ((2*64*LDA + 2*64*LDB) * 2)    // 36864 B
extern __shared__ __half smh[];

// ---------------- utility kernels ----------------
__global__ void k_split(const float* __restrict__ s, __half* __restrict__ d1,
                        __half* __restrict__ d2, int n) {
    int i = blockIdx.x * blockDim.x + threadIdx.x;
    for (; i < n; i += gridDim.x * blockDim.x) {
        float v = s[i];
        __half h1 = __float2half_rn(v);
        d1[i] = h1;
        d2[i] = __float2half_rn(v - __half2float(h1));
    }
}
__global__ void k_zero_state() {
    int i = blockIdx.x * blockDim.x + threadIdx.x;
    if (i < Bz * Hz) {
        __half z = __float2half(0.f);
        g_h1[0][i] = z; g_h1[1][i] = z; g_h2[0][i] = z; g_h2[1][i] = z; g_c[i] = 0.f;
    }
}
__global__ void k_hd_init() {
    int i = blockIdx.x * blockDim.x + threadIdx.x;
    if (i < Bz * Hz) {
        float v = g_htmp[i];
        __half h1 = __float2half_rn(v);
        g_h1[0][i] = h1;
        g_h2[0][i] = __float2half_rn(v - __half2float(h1));
        g_c[i] = 0.f;
    }
}
__global__ void k_copy_half(int off) {
    int i = blockIdx.x * blockDim.x + threadIdx.x;
    if (i < Bz * Hz) {
        int b = i >> 9, j = i & (Hz - 1);
        g_hcat[b * (2 * Hz) + off + j] = __half2float(g_h1[0][i]) + __half2float(g_h2[0][i]);
    }
}
__global__ void k_reparam(const float* __restrict__ eps, const float* __restrict__ muv,
                          const float* __restrict__ lvv) {
    int i = blockIdx.x * blockDim.x + threadIdx.x;
    if (i < Bz * Lz) g_z[i] = muv[i] + eps[i] * expf(0.5f * lvv[i]);
}

// ---------------- fp32 small GEMM (mu/lv/zp/hd) — proven in R2 ----------------
__global__ __launch_bounds__(256) void k_gemm(int K,
                                              const float* __restrict__ Bw, int ldb,
                                              const float* __restrict__ bias,
                                              float* __restrict__ Cext, int ldc,
                                              int a_sel, int c_sel) {
    const float* A = (a_sel == 1) ? g_hcat : g_z;
    float* C = (c_sel == 1) ? g_zp : (c_sel == 2) ? g_htmp : Cext;
    int lda = (a_sel == 1) ? 2 * Hz : Lz;
    __shared__ float As[16][68];
    __shared__ float Bs[16][68];
    const int tid = threadIdx.x;
    const int m0 = blockIdx.y * 64, n0 = blockIdx.x * 64;
    const int lr = tid >> 2, lk = tid & 3;
    const int tx = tid & 15, ty = tid >> 4;
    float acc[4][4] = {};
    for (int k0 = 0; k0 < K; k0 += 16) {
        float4 av = *(const float4*)(A + (size_t)(m0 + lr) * lda + k0 + lk * 4);
        float4 bv = *(const float4*)(Bw + (size_t)(n0 + lr) * ldb + k0 + lk * 4);
        __syncthreads();
        As[lk*4+0][lr]=av.x; As[lk*4+1][lr]=av.y; As[lk*4+2][lr]=av.z; As[lk*4+3][lr]=av.w;
        Bs[lk*4+0][lr]=bv.x; Bs[lk*4+1][lr]=bv.y; Bs[lk*4+2][lr]=bv.z; Bs[lk*4+3][lr]=bv.w;
        __syncthreads();
#pragma unroll
        for (int k = 0; k < 16; k++) {
            float4 a = *(const float4*)&As[k][ty*4];
            float4 b = *(const float4*)&Bs[k][tx*4];
            acc[0][0]+=a.x*b.x; acc[0][1]+=a.x*b.y; acc[0][2]+=a.x*b.z; acc[0][3]+=a.x*b.w;
            acc[1][0]+=a.y*b.x; acc[1][1]+=a.y*b.y; acc[1][2]+=a.y*b.z; acc[1][3]+=a.y*b.w;
            acc[2][0]+=a.z*b.x; acc[2][1]+=a.z*b.y; acc[2][2]+=a.z*b.z; acc[2][3]+=a.z*b.w;
            acc[3][0]+=a.w*b.x; acc[3][1]+=a.w*b.y; acc[3][2]+=a.w*b.z; acc[3][3]+=a.w*b.w;
        }
    }
#pragma unroll
    for (int i = 0; i < 4; i++)
#pragma unroll
        for (int j = 0; j < 4; j++) {
            int n = n0 + tx * 4 + j;
            float bb = bias ? bias[n] : 0.0f;
            C[(size_t)(m0 + ty * 4 + i) * ldc + n] = acc[i][j] + bb;
        }
}

// =============================================================================
// Split-fp16 MMA kernels. Common geometry per CTA:
//   BM=64 rows (m), BN=128 cols = 4 gates x 32 j (j-block j0).
//   n-local layout: nl = wn*32 + q*8 + s  ->  weight row q*Hz + j0 + wn*8 + s.
//   8 warps: wm = warp>>2 (m half), wn = warp&3 (j-subgroup of 8, all 4 gates).
//   Fragments loaded by direct LDS at documented thread coords:
//     g = lane>>2, i2 = (lane&3)*2
//     A: a0=[g][k+i2] a1=[g+8][k+i2] a2=[g][k+i2+8] a3=[g+8][k+i2+8]
//     B: b0=[n=g][k+i2] b1=[n=g][k+i2+8]
//     C: c0,c1=(row g, col i2,i2+1) c2,c3=(row g+8)
// =============================================================================

__device__ __forceinline__ void load_afrag(unsigned* f, const __half* A, int rbase) {
    f[0] = *(const unsigned*)(A + rbase);
    f[1] = *(const unsigned*)(A + rbase + 8 * LDA);
    f[2] = *(const unsigned*)(A + rbase + 8);
    f[3] = *(const unsigned*)(A + rbase + 8 * LDA + 8);
}

// ---------------- fused LSTM step: g = h@Whh^T + P[t]; gates; update ----------------
__global__ __launch_bounds__(256) void k_steph(int t, int pin,
                                               const __half* __restrict__ U1,
                                               const __half* __restrict__ U2,
                                               int store_hs) {
    __half* A1 = smh;
    __half* A2 = smh + 64 * LDA;
    __half* B1 = smh + 2 * 64 * LDA;
    __half* B2 = smh + 2 * 64 * LDA + 128 * LDB;
    const int tid = threadIdx.x;
    const int j0 = blockIdx.x * 32, b0 = blockIdx.y * 64;
    const __half* h1 = g_h1[pin];
    const __half* h2 = g_h2[pin];
    const int lane = tid & 31, warp = tid >> 5;
    const int wm = warp >> 2, wn = warp & 3;
    const int g = lane >> 2, i2 = (lane & 3) * 2;
    float acc[2][4][4] = {};

    for (int kc = 0; kc < 8; kc++) {
        int k0 = kc * 64;
        __syncthreads();
#pragma unroll
        for (int it = 0; it < 2; it++) {
            int c = tid + it * 256, r = c >> 3, col = (c & 7) * 8;
            *(uint4*)(A1 + r * LDA + col) = *(const uint4*)(h1 + (size_t)(b0 + r) * Hz + k0 + col);
            *(uint4*)(A2 + r * LDA + col) = *(const uint4*)(h2 + (size_t)(b0 + r) * Hz + k0 + col);
        }
#pragma unroll
        for (int it = 0; it < 4; it++) {
            int c = tid + it * 256, r = c >> 3, col = (c & 7) * 8;
            int q = (r >> 3) & 3, wnr = r >> 5, s = r & 7;
            size_t goff = (size_t)(q * Hz + j0 + wnr * 8 + s) * Hz + k0 + col;
            *(uint4*)(B1 + r * LDB + col) = *(const uint4*)(U1 + goff);
            *(uint4*)(B2 + r * LDB + col) = *(const uint4*)(U2 + goff);
        }
        __syncthreads();
#pragma unroll
        for (int kk = 0; kk < 4; kk++) {
            int k = kk * 16;
            unsigned a1f[2][4], a2f[2][4], b1f[4][2], b2f[4][2];
#pragma unroll
            for (int mt = 0; mt < 2; mt++) {
                int rbase = (wm * 32 + mt * 16 + g) * LDA + k + i2;
                load_afrag(a1f[mt], A1, rbase);
                load_afrag(a2f[mt], A2, rbase);
            }
#pragma unroll
            for (int q = 0; q < 4; q++) {
                int rb = (wn * 32 + q * 8 + g) * LDB + k + i2;
                b1f[q][0] = *(const unsigned*)(B1 + rb);
                b1f[q][1] = *(const unsigned*)(B1 + rb + 8);
                b2f[q][0] = *(const unsigned*)(B2 + rb);
                b2f[q][1] = *(const unsigned*)(B2 + rb + 8);
            }
#pragma unroll
            for (int mt = 0; mt < 2; mt++)
#pragma unroll
                for (int q = 0; q < 4; q++) {
                    mma16816(acc[mt][q], a1f[mt], b1f[q][0], b1f[q][1]);
                    mma16816(acc[mt][q], a1f[mt], b2f[q][0], b2f[q][1]);
                    mma16816(acc[mt][q], a2f[mt], b1f[q][0], b1f[q][1]);
                }
        }
    }
    // register-only gate epilogue
    __half* o1 = g_h1[pin ^ 1];
    __half* o2 = g_h2[pin ^ 1];
#pragma unroll
    for (int mt = 0; mt < 2; mt++)
#pragma unroll
        for (int rs = 0; rs < 2; rs++)
#pragma unroll
            for (int jj = 0; jj < 2; jj++) {
                int b = b0 + wm * 32 + mt * 16 + g + rs * 8;
                int j = j0 + wn * 8 + i2 + jj;
                int ci = rs * 2 + jj;
                size_t prow = ((size_t)t * Bz + b) * G4z;
                float gi = acc[mt][0][ci] + g_P[prow + j];
                float gf = acc[mt][1][ci] + g_P[prow + Hz + j];
                float gg = acc[mt][2][ci] + g_P[prow + 2 * Hz + j];
                float go = acc[mt][3][ci] + g_P[prow + 3 * Hz + j];
                int idx = b * Hz + j;
                float cn = sigm(gf) * g_c[idx] + sigm(gi) * tanhf(gg);
                float hn = sigm(go) * tanhf(cn);
                g_c[idx] = cn;
                __half hh1 = __float2half_rn(hn);
                __half hh2 = __float2half_rn(hn - __half2float(hh1));
                o1[idx] = hh1;
                o2[idx] = hh2;
                if (store_hs) {
                    size_t hi = ((size_t)t * Bz + b) * Hz + j;
                    g_hs1[hi] = hh1;
                    g_hs2[hi] = hh2;
                }
            }
}

// ---------------- input projection: P[m][q*H+j] = emb[tok(m)]@W^T + b (+zp) ----------------
__global__ __launch_bounds__(256) void k_projh(const int* __restrict__ ids, int rev,
                                               const __half* __restrict__ W1,
                                               const __half* __restrict__ W2, int ldw,
                                               const float* __restrict__ bias, int use_zp) {
    __half* A1 = smh;
    __half* A2 = smh + 64 * LDA;
    __half* B1 = smh + 2 * 64 * LDA;
    __half* B2 = smh + 2 * 64 * LDA + 128 * LDB;
    __shared__ int toks[64];
    const int tid = threadIdx.x;
    const int j0 = blockIdx.x * 32, m0 = blockIdx.y * 64;
    if (tid < 64) {
        int m = m0 + tid, b = m & (Bz - 1), t = m >> 9;
        int tt = rev ? (Tz - 1 - t) : t;
        toks[tid] = ids[b * Tz + tt];
    }
    const int lane = tid & 31, warp = tid >> 5;
    const int wm = warp >> 2, wn = warp & 3;
    const int g = lane >> 2, i2 = (lane & 3) * 2;
    float acc[2][4][4] = {};

    for (int kc = 0; kc < 4; kc++) {
        int k0 = kc * 64;
        __syncthreads();
#pragma unroll
        for (int it = 0; it < 2; it++) {
            int c = tid + it * 256, r = c >> 3, col = (c & 7) * 8;
            *(uint4*)(A1 + r * LDA + col) = *(const uint4*)(g_e1 + (size_t)toks[r] * Ez + k0 + col);
            *(uint4*)(A2 + r * LDA + col) = *(const uint4*)(g_e2 + (size_t)toks[r] * Ez + k0 + col);
        }
#pragma unroll
        for (int it = 0; it < 4; it++) {
            int c = tid + it * 256, r = c >> 3, col = (c & 7) * 8;
            int q = (r >> 3) & 3, wnr = r >> 5, s = r & 7;
            size_t goff = (size_t)(q * Hz + j0 + wnr * 8 + s) * ldw + k0 + col;
            *(uint4*)(B1 + r * LDB + col) = *(const uint4*)(W1 + goff);
            *(uint4*)(B2 + r * LDB + col) = *(const uint4*)(W2 + goff);
        }
        __syncthreads();
#pragma unroll
        for (int kk = 0; kk < 4; kk++) {
            int k = kk * 16;
            unsigned a1f[2][4], a2f[2][4], b1f[4][2], b2f[4][2];
#pragma unroll
            for (int mt = 0; mt < 2; mt++) {
                int rbase = (wm * 32 + mt * 16 + g) * LDA + k + i2;
                load_afrag(a1f[mt], A1, rbase);
                load_afrag(a2f[mt], A2, rbase);
            }
#pragma unroll
            for (int q = 0; q < 4; q++) {
                int rb = (wn * 32 + q * 8 + g) * LDB + k + i2;
                b1f[q][0] = *(const unsigned*)(B1 + rb);
                b1f[q][1] = *(const unsigned*)(B1 + rb + 8);
                b2f[q][0] = *(const unsigned*)(B2 + rb);
                b2f[q][1] = *(const unsigned*)(B2 + rb + 8);
            }
#pragma unroll
            for (int mt = 0; mt < 2; mt++)
#pragma unroll
                for (int q = 0; q < 4; q++) {
                    mma16816(acc[mt][q], a1f[mt], b1f[q][0], b1f[q][1]);
                    mma16816(acc[mt][q], a1f[mt], b2f[q][0], b2f[q][1]);
                    mma16816(acc[mt][q], a2f[mt], b1f[q][0], b1f[q][1]);
                }
        }
    }
#pragma unroll
    for (int mt = 0; mt < 2; mt++)
#pragma unroll
        for (int rs = 0; rs < 2; rs++)
#pragma unroll
            for (int jj = 0; jj < 2; jj++) {
                int m = m0 + wm * 32 + mt * 16 + g + rs * 8;
                int b = m & (Bz - 1);
                int ci = rs * 2 + jj;
#pragma unroll
                for (int q = 0; q < 4; q++) {
                    int n = q * Hz + j0 + wn * 8 + i2 + jj;
                    float v = acc[mt][q][ci] + bias[n];
                    if (use_zp) v += g_zp[(size_t)b * G4z + n];
                    g_P[(size_t)m * G4z + n] = v;
                }
            }
}

// ---------------- output head: out[b][t][v] = hs[m]@Wout^T + b_out ----------------
// BM=64 m, BN=64 v. wn owns v-range wn*16 (2 subtiles of 8).
__global__ __launch_bounds__(256) void k_outheadh(const float* __restrict__ bout,
                                                  float* __restrict__ out) {
    __half* A1 = smh;
    __half* A2 = smh + 64 * LDA;
    __half* B1 = smh + 2 * 64 * LDA;
    __half* B2 = smh + 2 * 64 * LDA + 64 * LDB;
    const int tid = threadIdx.x;
    const int m0 = blockIdx.x * 64;
    const int lane = tid & 31, warp = tid >> 5;
    const int wm = warp >> 2, wn = warp & 3;
    const int g = lane >> 2, i2 = (lane & 3) * 2;
    float acc[2][2][4] = {};

    for (int kc = 0; kc < 8; kc++) {
        int k0 = kc * 64;
        __syncthreads();
#pragma unroll
        for (int it = 0; it < 2; it++) {
            int c = tid + it * 256, r = c >> 3, col = (c & 7) * 8;
            *(uint4*)(A1 + r * LDA + col) = *(const uint4*)(g_hs1 + (size_t)(m0 + r) * Hz + k0 + col);
            *(uint4*)(A2 + r * LDA + col) = *(const uint4*)(g_hs2 + (size_t)(m0 + r) * Hz + k0 + col);
            *(uint4*)(B1 + r * LDB + col) = *(const uint4*)(g_Wo1 + (size_t)r * Hz + k0 + col);
            *(uint4*)(B2 + r * LDB + col) = *(const uint4*)(g_Wo2 + (size_t)r * Hz + k0 + col);
        }
        __syncthreads();
#pragma unroll
        for (int kk = 0; kk < 4; kk++) {
            int k = kk * 16;
            unsigned a1f[2][4], a2f[2][4], b1f[2][2], b2f[2][2];
#pragma unroll
            for (int mt = 0; mt < 2; mt++) {
                int rbase = (wm * 32 + mt * 16 + g) * LDA + k + i2;
                load_afrag(a1f[mt], A1, rbase);
                load_afrag(a2f[mt], A2, rbase);
            }
#pragma unroll
            for (int nt = 0; nt < 2; nt++) {
                int rb = (wn * 16 + nt * 8 + g) * LDB + k + i2;
                b1f[nt][0] = *(const unsigned*)(B1 + rb);
                b1f[nt][1] = *(const unsigned*)(B1 + rb + 8);
                b2f[nt][0] = *(const unsigned*)(B2 + rb);
                b2f[nt][1] = *(const unsigned*)(B2 + rb + 8);
            }
#pragma unroll
            for (int mt = 0; mt < 2; mt++)
#pragma unroll
                for (int nt = 0; nt < 2; nt++) {
                    mma16816(acc[mt][nt], a1f[mt], b1f[nt][0], b1f[nt][1]);
                    mma16816(acc[mt][nt], a1f[mt], b2f[nt][0], b2f[nt][1]);
                    mma16816(acc[mt][nt], a2f[mt], b1f[nt][0], b1f[nt][1]);
                }
        }
    }
#pragma unroll
    for (int mt = 0; mt < 2; mt++)
#pragma unroll
        for (int rs = 0; rs < 2; rs++)
#pragma unroll
            for (int jj = 0; jj < 2; jj++) {
                int m = m0 + wm * 32 + mt * 16 + g + rs * 8;
                int b = m & (Bz - 1), tt = m >> 9;
                int ci = rs * 2 + jj;
#pragma unroll
                for (int nt = 0; nt < 2; nt++) {
                    int v = wn * 16 + nt * 8 + i2 + jj;
                    out[((size_t)b * Tz + tt) * Vz + v] = acc[mt][nt][ci] + bout[v];
                }
            }
}

// ---------------- launch ----------------
extern "C" void kernel_launch(void* const* d_in, const int* in_sizes, int n_in,
                              void* d_out, int out_size) {
    const int* x   = (const int*)d_in[0];
    const int* tgt = (const int*)d_in[1];
    const float* eps   = (const float*)d_in[2];
    const float* emb   = (const float*)d_in[3];
    const float* Wih_f = (const float*)d_in[4];
    const float* Whh_f = (const float*)d_in[5];
    const float* b_f   = (const float*)d_in[6];
    const float* Wih_b = (const float*)d_in[7];
    const float* Whh_b = (const float*)d_in[8];
    const float* b_b   = (const float*)d_in[9];
    const float* W_mu  = (const float*)d_in[10];
    const float* b_mu  = (const float*)d_in[11];
    const float* W_lv  = (const float*)d_in[12];
    const float* b_lv  = (const float*)d_in[13];
    const float* W_di  = (const float*)d_in[14];
    const float* b_di  = (const float*)d_in[15];
    const float* Wih_d = (const float*)d_in[16];
    const float* Whh_d = (const float*)d_in[17];
    const float* b_d   = (const float*)d_in[18];
    const float* W_out = (const float*)d_in[19];
    const float* b_out = (const float*)d_in[20];

    float* out  = (float*)d_out;
    float* mu_o = out + (size_t)Bz * Tz * Vz;
    float* lv_o = mu_o + Bz * Lz;

    cudaFuncSetAttribute(k_projh,    cudaFuncAttributeMaxDynamicSharedMemorySize, SMEM_STEP);
    cudaFuncSetAttribute(k_steph,    cudaFuncAttributeMaxDynamicSharedMemorySize, SMEM_STEP);
    cudaFuncSetAttribute(k_outheadh, cudaFuncAttributeMaxDynamicSharedMemorySize, SMEM_OUT);

    __half *e1, *e2, *wf1, *wf2, *wb1, *wb2, *wd1, *wd2;
    __half *uf1, *uf2, *ub1, *ub2, *ud1, *ud2, *wo1, *wo2;
    cudaGetSymbolAddress((void**)&e1, g_e1);   cudaGetSymbolAddress((void**)&e2, g_e2);
    cudaGetSymbolAddress((void**)&wf1, g_Wf1); cudaGetSymbolAddress((void**)&wf2, g_Wf2);
    cudaGetSymbolAddress((void**)&wb1, g_Wb1); cudaGetSymbolAddress((void**)&wb2, g_Wb2);
    cudaGetSymbolAddress((void**)&wd1, g_Wd1); cudaGetSymbolAddress((void**)&wd2, g_Wd2);
    cudaGetSymbolAddress((void**)&uf1, g_Uf1); cudaGetSymbolAddress((void**)&uf2, g_Uf2);
    cudaGetSymbolAddress((void**)&ub1, g_Ub1); cudaGetSymbolAddress((void**)&ub2, g_Ub2);
    cudaGetSymbolAddress((void**)&ud1, g_Ud1); cudaGetSymbolAddress((void**)&ud2, g_Ud2);
    cudaGetSymbolAddress((void**)&wo1, g_Wo1); cudaGetSymbolAddress((void**)&wo2, g_Wo2);

    k_split<<<64, 256>>>(emb, e1, e2, Vz * Ez);
    k_split<<<512, 256>>>(Wih_f, wf1, wf2, G4z * Ez);
    k_split<<<512, 256>>>(Wih_b, wb1, wb2, G4z * Ez);
    k_split<<<512, 256>>>(Wih_d, wd1, wd2, G4z * ELz);
    k_split<<<512, 256>>>(Whh_f, uf1, uf2, G4z * Hz);
    k_split<<<512, 256>>>(Whh_b, ub1, ub2, G4z * Hz);
    k_split<<<512, 256>>>(Whh_d, ud1, ud2, G4z * Hz);
    k_split<<<64, 256>>>(W_out, wo1, wo2, Vz * Hz);

    dim3 projGrid(Hz / 32, (Tz * Bz) / 64);   // (16, 1024)
    dim3 stepGrid(Hz / 32, Bz / 64);          // (16, 8)
    int zeroBlocks = (Bz * Hz + 255) / 256;

    // ---- encoder forward ----
    k_projh<<<projGrid, 256, SMEM_STEP>>>(x, 0, wf1, wf2, Ez, b_f, 0);
    k_zero_state<<<zeroBlocks, 256>>>();
    for (int t = 0; t < Tz; t++) k_steph<<<stepGrid, 256, SMEM_STEP>>>(t, t & 1, uf1, uf2, 0);
    k_copy_half<<<zeroBlocks, 256>>>(0);

    // ---- encoder backward ----
    k_projh<<<projGrid, 256, SMEM_STEP>>>(x, 1, wb1, wb2, Ez, b_b, 0);
    k_zero_state<<<zeroBlocks, 256>>>();
    for (int t = 0; t < Tz; t++) k_steph<<<stepGrid, 256, SMEM_STEP>>>(t, t & 1, ub1, ub2, 0);
    k_copy_half<<<zeroBlocks, 256>>>(Hz);

    // ---- latent heads + reparameterize (fp32) ----
    k_gemm<<<dim3(Lz / 64, Bz / 64), 256>>>(2 * Hz, W_mu, 2 * Hz, b_mu, mu_o, Lz, 1, 0);
    k_gemm<<<dim3(Lz / 64, Bz / 64), 256>>>(2 * Hz, W_lv, 2 * Hz, b_lv, lv_o, Lz, 1, 0);
    k_reparam<<<(Bz * Lz + 255) / 256, 256>>>(eps, mu_o, lv_o);

    // ---- decoder prologue ----
    k_gemm<<<dim3(G4z / 64, Bz / 64), 256>>>(Lz, Wih_d + Ez, ELz, nullptr, nullptr, G4z, 2, 1); // zp
    k_projh<<<projGrid, 256, SMEM_STEP>>>(tgt, 0, wd1, wd2, ELz, b_d, 1);
    k_gemm<<<dim3(Hz / 64, Bz / 64), 256>>>(Lz, W_di, Lz, b_di, nullptr, Hz, 2, 2);             // g_htmp
    k_hd_init<<<zeroBlocks, 256>>>();

    // ---- decoder recurrence ----
    for (int t = 0; t < Tz; t++) k_steph<<<stepGrid, 256, SMEM_STEP>>>(t, t & 1, ud1, ud2, 1);

    // ---- output head ----
    k_outheadh<<<(Tz * Bz) / 64, 256, SMEM_OUT>>>(b_out, out);
}

// round 5
// speedup vs baseline: 3.8372x; 1.5692x over previous
#include <cuda_runtime.h>
#include <cuda_fp16.h>
#include <math.h>

#define Bz 512
#define Tz 128
#define Vz 64
#define Ez 256
#define Hz 512
#define Lz 128
#define G4z 2048
#define ELz 384
#define LDA 72
#define LDB 72

// ---------------- scratch ----------------
__device__ __align__(16) __half g_h1[2][Bz * Hz];
__device__ __align__(16) __half g_h2[2][Bz * Hz];
__device__ __align__(16) float  g_c[Bz * Hz];
__device__ __align__(16) float  g_htmp[Bz * Hz];
__device__ __align__(16) float  g_hcat[Bz * 2 * Hz];
__device__ __align__(16) float  g_z[Bz * Lz];
__device__ __align__(16) float  g_zp[Bz * G4z];
__device__ __align__(16) __half g_hs1[(size_t)Tz * Bz * Hz];
__device__ __align__(16) __half g_hs2[(size_t)Tz * Bz * Hz];
// embedding projection tables: E[v][n] = emb[v]@Wih^T + b  (fp32, 64 x 2048 each)
__device__ __align__(16) float  g_EF[Vz * G4z];
__device__ __align__(16) float  g_EB[Vz * G4z];
__device__ __align__(16) float  g_ED[Vz * G4z];
// split-fp16 weights
__device__ __align__(16) __half g_Uf1[G4z * Hz], g_Uf2[G4z * Hz];
__device__ __align__(16) __half g_Ub1[G4z * Hz], g_Ub2[G4z * Hz];
__device__ __align__(16) __half g_Ud1[G4z * Hz], g_Ud2[G4z * Hz];
__device__ __align__(16) __half g_Wo1[Vz * Hz],  g_Wo2[Vz * Hz];

__device__ __forceinline__ float sigm(float x) { return 1.0f / (1.0f + expf(-x)); }

__device__ __forceinline__ void mma16816(float* d, const unsigned* a, unsigned b0, unsigned b1) {
    asm volatile("mma.sync.aligned.m16n8k16.row.col.f32.f16.f16.f32 "
                 "{%0,%1,%2,%3},{%4,%5,%6,%7},{%8,%9},{%0,%1,%2,%3};"
                 : "+f"(d[0]), "+f"(d[1]), "+f"(d[2]), "+f"(d[3])
                 : "r"(a[0]), "r"(a[1]), "r"(a[2]), "r"(a[3]), "r"(b0), "r"(b1));
}
__device__ __forceinline__ unsigned su(const void* p) {
    return (unsigned)__cvta_generic_to_shared(p);
}
__device__ __forceinline__ void cpa16(void* dst, const void* src) {
    asm volatile("cp.async.cg.shared.global [%0], [%1], 16;" :: "r"(su(dst)), "l"(src));
}
#define CP_COMMIT() asm volatile("cp.async.commit_group;")
#define CP_WAIT1()  asm volatile("cp.async.wait_group 1;")
#define CP_WAIT0()  asm volatile("cp.async.wait_group 0;")

// step smem: 2 stages x {A1,A2: 64xLDA, B1,B2: 128xLDB} halves
#define SMEM_STEP (4*64*LDA*2 + 4*128*LDB*2)   // 110592 B
#define SMEM_OUT  ((2*64*LDA + 2*64*LDB) * 2)  // 36864 B
extern __shared__ __half smh[];

__device__ __forceinline__ void load_afrag(unsigned* f, const __half* A, int rbase) {
    f[0] = *(const unsigned*)(A + rbase);
    f[1] = *(const unsigned*)(A + rbase + 8 * LDA);
    f[2] = *(const unsigned*)(A + rbase + 8);
    f[3] = *(const unsigned*)(A + rbase + 8 * LDA + 8);
}

// ---------------- utility kernels ----------------
__global__ void k_split(const float* __restrict__ s, __half* __restrict__ d1,
                        __half* __restrict__ d2, int n) {
    int i = blockIdx.x * blockDim.x + threadIdx.x;
    for (; i < n; i += gridDim.x * blockDim.x) {
        float v = s[i];
        __half h1 = __float2half_rn(v);
        d1[i] = h1;
        d2[i] = __float2half_rn(v - __half2float(h1));
    }
}
__global__ void k_zero_state() {
    int i = blockIdx.x * blockDim.x + threadIdx.x;
    if (i < Bz * Hz) {
        __half zz = __float2half(0.f);
        g_h1[0][i] = zz; g_h1[1][i] = zz; g_h2[0][i] = zz; g_h2[1][i] = zz; g_c[i] = 0.f;
    }
}
__global__ void k_hd_init() {
    int i = blockIdx.x * blockDim.x + threadIdx.x;
    if (i < Bz * Hz) {
        float v = g_htmp[i];
        __half h1 = __float2half_rn(v);
        g_h1[0][i] = h1;
        g_h2[0][i] = __float2half_rn(v - __half2float(h1));
        g_c[i] = 0.f;
    }
}
__global__ void k_copy_half(int off) {
    int i = blockIdx.x * blockDim.x + threadIdx.x;
    if (i < Bz * Hz) {
        int b = i >> 9, j = i & (Hz - 1);
        g_hcat[b * (2 * Hz) + off + j] = __half2float(g_h1[0][i]) + __half2float(g_h2[0][i]);
    }
}
__global__ void k_reparam(const float* __restrict__ eps, const float* __restrict__ muv,
                          const float* __restrict__ lvv) {
    int i = blockIdx.x * blockDim.x + threadIdx.x;
    if (i < Bz * Lz) g_z[i] = muv[i] + eps[i] * expf(0.5f * lvv[i]);
}

// ---------------- fp32 GEMM: C[M,N] = A[M,K]@Bw[N,K]^T (+bias), all ptrs explicit ------
__global__ __launch_bounds__(256) void k_gemm(int K,
                                              const float* __restrict__ A, int lda,
                                              const float* __restrict__ Bw, int ldb,
                                              const float* __restrict__ bias,
                                              float* __restrict__ C, int ldc) {
    __shared__ float As[16][68];
    __shared__ float Bs[16][68];
    const int tid = threadIdx.x;
    const int m0 = blockIdx.y * 64, n0 = blockIdx.x * 64;
    const int lr = tid >> 2, lk = tid & 3;
    const int tx = tid & 15, ty = tid >> 4;
    float acc[4][4] = {};
    for (int k0 = 0; k0 < K; k0 += 16) {
        float4 av = *(const float4*)(A + (size_t)(m0 + lr) * lda + k0 + lk * 4);
        float4 bv = *(const float4*)(Bw + (size_t)(n0 + lr) * ldb + k0 + lk * 4);
        __syncthreads();
        As[lk*4+0][lr]=av.x; As[lk*4+1][lr]=av.y; As[lk*4+2][lr]=av.z; As[lk*4+3][lr]=av.w;
        Bs[lk*4+0][lr]=bv.x; Bs[lk*4+1][lr]=bv.y; Bs[lk*4+2][lr]=bv.z; Bs[lk*4+3][lr]=bv.w;
        __syncthreads();
#pragma unroll
        for (int k = 0; k < 16; k++) {
            float4 a = *(const float4*)&As[k][ty*4];
            float4 b = *(const float4*)&Bs[k][tx*4];
            acc[0][0]+=a.x*b.x; acc[0][1]+=a.x*b.y; acc[0][2]+=a.x*b.z; acc[0][3]+=a.x*b.w;
            acc[1][0]+=a.y*b.x; acc[1][1]+=a.y*b.y; acc[1][2]+=a.y*b.z; acc[1][3]+=a.y*b.w;
            acc[2][0]+=a.z*b.x; acc[2][1]+=a.z*b.y; acc[2][2]+=a.z*b.z; acc[2][3]+=a.z*b.w;
            acc[3][0]+=a.w*b.x; acc[3][1]+=a.w*b.y; acc[3][2]+=a.w*b.z; acc[3][3]+=a.w*b.w;
        }
    }
#pragma unroll
    for (int i = 0; i < 4; i++)
#pragma unroll
        for (int j = 0; j < 4; j++) {
            int n = n0 + tx * 4 + j;
            float bb = bias ? bias[n] : 0.0f;
            C[(size_t)(m0 + ty * 4 + i) * ldc + n] = acc[i][j] + bb;
        }
}

// ---------------- fused LSTM step, split-fp16 3-MMA, cp.async double-buffered ----------
// BM=64 batch, BN=128 (4 gates x 32 j), K=512. 512 threads, 16 warps (4m x 4n),
// warp tile 16m x 32n. grid (16, 8).
__global__ __launch_bounds__(512) void k_steph(int t, int pin,
                                               const __half* __restrict__ U1,
                                               const __half* __restrict__ U2,
                                               const int* __restrict__ ids, int rev,
                                               const float* __restrict__ E,
                                               int use_zp, int store_hs) {
    __shared__ int toks[64];
    const int tid = threadIdx.x;
    const int j0 = blockIdx.x * 32, b0 = blockIdx.y * 64;
    const __half* h1 = g_h1[pin];
    const __half* h2 = g_h2[pin];
    const int lane = tid & 31, warp = tid >> 5;
    const int wm = warp >> 2, wn = warp & 3;
    const int g = lane >> 2, i2 = (lane & 3) * 2;

    if (tid < 64) {
        int tt = rev ? (Tz - 1 - t) : t;
        toks[tid] = ids[(b0 + tid) * Tz + tt];
    }

    // smem layout
    __half* Abase = smh;                 // [stage][arr][64][LDA]
    __half* Bbase = smh + 4 * 64 * LDA;  // [stage][arr][128][LDB]
#define A_ST(st, arr) (Abase + ((st)*2 + (arr)) * 64 * LDA)
#define B_ST(st, arr) (Bbase + ((st)*2 + (arr)) * 128 * LDB)

    // stage loader (512 threads)
    auto stage_load = [&](int st, int k0) {
        {
            int r = tid >> 3, col = (tid & 7) * 8;
            const size_t off = (size_t)(b0 + r) * Hz + k0 + col;
            cpa16(A_ST(st, 0) + r * LDA + col, h1 + off);
            cpa16(A_ST(st, 1) + r * LDA + col, h2 + off);
        }
#pragma unroll
        for (int it = 0; it < 2; it++) {
            int c = tid + it * 512, r = c >> 3, col = (c & 7) * 8;
            int q = (r >> 3) & 3, wnr = r >> 5, s = r & 7;
            size_t goff = (size_t)(q * Hz + j0 + wnr * 8 + s) * Hz + k0 + col;
            cpa16(B_ST(st, 0) + r * LDB + col, U1 + goff);
            cpa16(B_ST(st, 1) + r * LDB + col, U2 + goff);
        }
    };

    float acc[4][4] = {};
    stage_load(0, 0);
    CP_COMMIT();

    for (int kc = 0; kc < 8; kc++) {
        if (kc < 7) {
            stage_load((kc + 1) & 1, (kc + 1) * 64);
            CP_COMMIT();
            CP_WAIT1();
        } else {
            CP_WAIT0();
        }
        __syncthreads();
        const __half* A1 = A_ST(kc & 1, 0);
        const __half* A2 = A_ST(kc & 1, 1);
        const __half* B1 = B_ST(kc & 1, 0);
        const __half* B2 = B_ST(kc & 1, 1);
#pragma unroll
        for (int kk = 0; kk < 4; kk++) {
            int k = kk * 16;
            unsigned a1f[4], a2f[4], b1f[4][2], b2f[4][2];
            int rbase = (wm * 16 + g) * LDA + k + i2;
            load_afrag(a1f, A1, rbase);
            load_afrag(a2f, A2, rbase);
#pragma unroll
            for (int q = 0; q < 4; q++) {
                int rb = (wn * 32 + q * 8 + g) * LDB + k + i2;
                b1f[q][0] = *(const unsigned*)(B1 + rb);
                b1f[q][1] = *(const unsigned*)(B1 + rb + 8);
                b2f[q][0] = *(const unsigned*)(B2 + rb);
                b2f[q][1] = *(const unsigned*)(B2 + rb + 8);
            }
#pragma unroll
            for (int q = 0; q < 4; q++) {
                mma16816(acc[q], a1f, b1f[q][0], b1f[q][1]);
                mma16816(acc[q], a1f, b2f[q][0], b2f[q][1]);
                mma16816(acc[q], a2f, b1f[q][0], b1f[q][1]);
            }
        }
        __syncthreads();
    }

    // epilogue: gather eproj (+zp), gates, state update
    __half* o1 = g_h1[pin ^ 1];
    __half* o2 = g_h2[pin ^ 1];
    const int jb = j0 + wn * 8 + i2;
#pragma unroll
    for (int rs = 0; rs < 2; rs++) {
        int r = wm * 16 + g + rs * 8;
        int b = b0 + r;
        int tok = toks[r];
        float2 gv[4];
#pragma unroll
        for (int q = 0; q < 4; q++) {
            int n = q * Hz + jb;
            float2 e = *(const float2*)&E[(size_t)tok * G4z + n];
            if (use_zp) {
                float2 zp2 = *(const float2*)&g_zp[(size_t)b * G4z + n];
                e.x += zp2.x; e.y += zp2.y;
            }
            gv[q] = make_float2(acc[q][rs * 2 + 0] + e.x, acc[q][rs * 2 + 1] + e.y);
        }
        int idx = b * Hz + jb;
        float2 cold = *(const float2*)&g_c[idx];
        float cn0 = sigm(gv[1].x) * cold.x + sigm(gv[0].x) * tanhf(gv[2].x);
        float cn1 = sigm(gv[1].y) * cold.y + sigm(gv[0].y) * tanhf(gv[2].y);
        float hn0 = sigm(gv[3].x) * tanhf(cn0);
        float hn1 = sigm(gv[3].y) * tanhf(cn1);
        *(float2*)&g_c[idx] = make_float2(cn0, cn1);
        __half p0 = __float2half_rn(hn0), p1 = __float2half_rn(hn1);
        __half q0 = __float2half_rn(hn0 - __half2float(p0));
        __half q1 = __float2half_rn(hn1 - __half2float(p1));
        *(__half2*)&o1[idx] = __halves2half2(p0, p1);
        *(__half2*)&o2[idx] = __halves2half2(q0, q1);
        if (store_hs) {
            size_t hi = ((size_t)t * Bz + b) * Hz + jb;
            *(__half2*)&g_hs1[hi] = __halves2half2(p0, p1);
            *(__half2*)&g_hs2[hi] = __halves2half2(q0, q1);
        }
    }
}

// ---------------- output head (R4-proven): out[b][t][v] = hs[m]@Wout^T + b_out ----------
__global__ __launch_bounds__(256) void k_outheadh(const float* __restrict__ bout,
                                                  float* __restrict__ out) {
    __half* A1 = smh;
    __half* A2 = smh + 64 * LDA;
    __half* B1 = smh + 2 * 64 * LDA;
    __half* B2 = smh + 2 * 64 * LDA + 64 * LDB;
    const int tid = threadIdx.x;
    const int m0 = blockIdx.x * 64;
    const int lane = tid & 31, warp = tid >> 5;
    const int wm = warp >> 2, wn = warp & 3;
    const int g = lane >> 2, i2 = (lane & 3) * 2;
    float acc[2][2][4] = {};

    for (int kc = 0; kc < 8; kc++) {
        int k0 = kc * 64;
        __syncthreads();
#pragma unroll
        for (int it = 0; it < 2; it++) {
            int c = tid + it * 256, r = c >> 3, col = (c & 7) * 8;
            *(uint4*)(A1 + r * LDA + col) = *(const uint4*)(g_hs1 + (size_t)(m0 + r) * Hz + k0 + col);
            *(uint4*)(A2 + r * LDA + col) = *(const uint4*)(g_hs2 + (size_t)(m0 + r) * Hz + k0 + col);
            *(uint4*)(B1 + r * LDB + col) = *(const uint4*)(g_Wo1 + (size_t)r * Hz + k0 + col);
            *(uint4*)(B2 + r * LDB + col) = *(const uint4*)(g_Wo2 + (size_t)r * Hz + k0 + col);
        }
        __syncthreads();
#pragma unroll
        for (int kk = 0; kk < 4; kk++) {
            int k = kk * 16;
            unsigned a1f[2][4], a2f[2][4], b1f[2][2], b2f[2][2];
#pragma unroll
            for (int mt = 0; mt < 2; mt++) {
                int rbase = (wm * 32 + mt * 16 + g) * LDA + k + i2;
                load_afrag(a1f[mt], A1, rbase);
                load_afrag(a2f[mt], A2, rbase);
            }
#pragma unroll
            for (int nt = 0; nt < 2; nt++) {
                int rb = (wn * 16 + nt * 8 + g) * LDB + k + i2;
                b1f[nt][0] = *(const unsigned*)(B1 + rb);
                b1f[nt][1] = *(const unsigned*)(B1 + rb + 8);
                b2f[nt][0] = *(const unsigned*)(B2 + rb);
                b2f[nt][1] = *(const unsigned*)(B2 + rb + 8);
            }
#pragma unroll
            for (int mt = 0; mt < 2; mt++)
#pragma unroll
                for (int nt = 0; nt < 2; nt++) {
                    mma16816(acc[mt][nt], a1f[mt], b1f[nt][0], b1f[nt][1]);
                    mma16816(acc[mt][nt], a1f[mt], b2f[nt][0], b2f[nt][1]);
                    mma16816(acc[mt][nt], a2f[mt], b1f[nt][0], b1f[nt][1]);
                }
        }
    }
#pragma unroll
    for (int mt = 0; mt < 2; mt++)
#pragma unroll
        for (int rs = 0; rs < 2; rs++)
#pragma unroll
            for (int jj = 0; jj < 2; jj++) {
                int m = m0 + wm * 32 + mt * 16 + g + rs * 8;
                int b = m & (Bz - 1), tt = m >> 9;
                int ci = rs * 2 + jj;
#pragma unroll
                for (int nt = 0; nt < 2; nt++) {
                    int v = wn * 16 + nt * 8 + i2 + jj;
                    out[((size_t)b * Tz + tt) * Vz + v] = acc[mt][nt][ci] + bout[v];
                }
            }
}

// ---------------- launch ----------------
extern "C" void kernel_launch(void* const* d_in, const int* in_sizes, int n_in,
                              void* d_out, int out_size) {
    const int* x   = (const int*)d_in[0];
    const int* tgt = (const int*)d_in[1];
    const float* eps   = (const float*)d_in[2];
    const float* emb   = (const float*)d_in[3];
    const float* Wih_f = (const float*)d_in[4];
    const float* Whh_f = (const float*)d_in[5];
    const float* b_f   = (const float*)d_in[6];
    const float* Wih_b = (const float*)d_in[7];
    const float* Whh_b = (const float*)d_in[8];
    const float* b_b   = (const float*)d_in[9];
    const float* W_mu  = (const float*)d_in[10];
    const float* b_mu  = (const float*)d_in[11];
    const float* W_lv  = (const float*)d_in[12];
    const float* b_lv  = (const float*)d_in[13];
    const float* W_di  = (const float*)d_in[14];
    const float* b_di  = (const float*)d_in[15];
    const float* Wih_d = (const float*)d_in[16];
    const float* Whh_d = (const float*)d_in[17];
    const float* b_d   = (const float*)d_in[18];
    const float* W_out = (const float*)d_in[19];
    const float* b_out = (const float*)d_in[20];

    float* out  = (float*)d_out;
    float* mu_o = out + (size_t)Bz * Tz * Vz;
    float* lv_o = mu_o + Bz * Lz;

    cudaFuncSetAttribute(k_steph,    cudaFuncAttributeMaxDynamicSharedMemorySize, SMEM_STEP);
    cudaFuncSetAttribute(k_outheadh, cudaFuncAttributeMaxDynamicSharedMemorySize, SMEM_OUT);

    __half *uf1, *uf2, *ub1, *ub2, *ud1, *ud2, *wo1, *wo2;
    float *ef, *eb, *ed, *hcat, *z, *zp, *htmp;
    cudaGetSymbolAddress((void**)&uf1, g_Uf1); cudaGetSymbolAddress((void**)&uf2, g_Uf2);
    cudaGetSymbolAddress((void**)&ub1, g_Ub1); cudaGetSymbolAddress((void**)&ub2, g_Ub2);
    cudaGetSymbolAddress((void**)&ud1, g_Ud1); cudaGetSymbolAddress((void**)&ud2, g_Ud2);
    cudaGetSymbolAddress((void**)&wo1, g_Wo1); cudaGetSymbolAddress((void**)&wo2, g_Wo2);
    cudaGetSymbolAddress((void**)&ef, g_EF);   cudaGetSymbolAddress((void**)&eb, g_EB);
    cudaGetSymbolAddress((void**)&ed, g_ED);
    cudaGetSymbolAddress((void**)&hcat, g_hcat);
    cudaGetSymbolAddress((void**)&z, g_z);
    cudaGetSymbolAddress((void**)&zp, g_zp);
    cudaGetSymbolAddress((void**)&htmp, g_htmp);

    k_split<<<512, 256>>>(Whh_f, uf1, uf2, G4z * Hz);
    k_split<<<512, 256>>>(Whh_b, ub1, ub2, G4z * Hz);
    k_split<<<512, 256>>>(Whh_d, ud1, ud2, G4z * Hz);
    k_split<<<64, 256>>>(W_out, wo1, wo2, Vz * Hz);

    // embedding projection tables (fp32): E = emb @ Wih^T + b   (M=64, N=2048)
    k_gemm<<<dim3(32, 1), 256>>>(Ez, emb, Ez, Wih_f, Ez, b_f, ef, G4z);
    k_gemm<<<dim3(32, 1), 256>>>(Ez, emb, Ez, Wih_b, Ez, b_b, eb, G4z);
    k_gemm<<<dim3(32, 1), 256>>>(Ez, emb, Ez, Wih_d, ELz, b_d, ed, G4z);

    dim3 stepGrid(Hz / 32, Bz / 64);   // (16, 8)
    int zeroBlocks = (Bz * Hz + 255) / 256;

    // ---- encoder forward ----
    k_zero_state<<<zeroBlocks, 256>>>();
    for (int t = 0; t < Tz; t++)
        k_steph<<<stepGrid, 512, SMEM_STEP>>>(t, t & 1, uf1, uf2, x, 0, ef, 0, 0);
    k_copy_half<<<zeroBlocks, 256>>>(0);

    // ---- encoder backward ----
    k_zero_state<<<zeroBlocks, 256>>>();
    for (int t = 0; t < Tz; t++)
        k_steph<<<stepGrid, 512, SMEM_STEP>>>(t, t & 1, ub1, ub2, x, 1, eb, 0, 0);
    k_copy_half<<<zeroBlocks, 256>>>(Hz);

    // ---- latent heads + reparameterize (fp32) ----
    k_gemm<<<dim3(Lz / 64, Bz / 64), 256>>>(2 * Hz, hcat, 2 * Hz, W_mu, 2 * Hz, b_mu, mu_o, Lz);
    k_gemm<<<dim3(Lz / 64, Bz / 64), 256>>>(2 * Hz, hcat, 2 * Hz, W_lv, 2 * Hz, b_lv, lv_o, Lz);
    k_reparam<<<(Bz * Lz + 255) / 256, 256>>>(eps, mu_o, lv_o);

    // ---- decoder prologue ----
    k_gemm<<<dim3(G4z / 64, Bz / 64), 256>>>(Lz, z, Lz, Wih_d + Ez, ELz, nullptr, zp, G4z);
    k_gemm<<<dim3(Hz / 64, Bz / 64), 256>>>(Lz, z, Lz, W_di, Lz, b_di, htmp, Hz);
    k_hd_init<<<zeroBlocks, 256>>>();

    // ---- decoder recurrence ----
    for (int t = 0; t < Tz; t++)
        k_steph<<<stepGrid, 512, SMEM_STEP>>>(t, t & 1, ud1, ud2, tgt, 0, ed, 1, 1);

    // ---- output head ----
    k_outheadh<<<(Tz * Bz) / 64, 256, SMEM_OUT>>>(b_out, out);
}

// round 6
// speedup vs baseline: 3.9939x; 1.0408x over previous
#include <cuda_runtime.h>
#include <cuda_fp16.h>
#include <math.h>

#define Bz 512
#define Tz 128
#define Vz 64
#define Ez 256
#define Hz 512
#define Lz 128
#define G4z 2048
#define ELz 384
#define LDA 72
#define LDB 72

// ---------------- scratch ----------------
// hidden state rows: 0..511 = fwd (or decoder), 512..1023 = bwd encoder
__device__ __align__(16) __half g_h1[2][2 * Bz * Hz];
__device__ __align__(16) __half g_h2[2][2 * Bz * Hz];
__device__ __align__(16) float  g_c[2 * Bz * Hz];
__device__ __align__(16) float  g_htmp[Bz * Hz];
__device__ __align__(16) float  g_hcat[Bz * 2 * Hz];
__device__ __align__(16) float  g_z[Bz * Lz];
__device__ __align__(16) float  g_zp[Bz * G4z];
__device__ __align__(16) __half g_hs1[(size_t)Tz * Bz * Hz];
__device__ __align__(16) __half g_hs2[(size_t)Tz * Bz * Hz];
// embedding projection tables: E[v][n] = emb[v]@Wih^T + b  (fp32, 64 x 2048)
__device__ __align__(16) float  g_EF[Vz * G4z];
__device__ __align__(16) float  g_EB[Vz * G4z];
__device__ __align__(16) float  g_ED[Vz * G4z];
// split-fp16 weights
__device__ __align__(16) __half g_Uf1[G4z * Hz], g_Uf2[G4z * Hz];
__device__ __align__(16) __half g_Ub1[G4z * Hz], g_Ub2[G4z * Hz];
__device__ __align__(16) __half g_Ud1[G4z * Hz], g_Ud2[G4z * Hz];
__device__ __align__(16) __half g_Wo1[Vz * Hz],  g_Wo2[Vz * Hz];

__device__ __forceinline__ float sigm(float x) { return 1.0f / (1.0f + expf(-x)); }

__device__ __forceinline__ void mma16816(float* d, const unsigned* a, unsigned b0, unsigned b1) {
    asm volatile("mma.sync.aligned.m16n8k16.row.col.f32.f16.f16.f32 "
                 "{%0,%1,%2,%3},{%4,%5,%6,%7},{%8,%9},{%0,%1,%2,%3};"
                 : "+f"(d[0]), "+f"(d[1]), "+f"(d[2]), "+f"(d[3])
                 : "r"(a[0]), "r"(a[1]), "r"(a[2]), "r"(a[3]), "r"(b0), "r"(b1));
}
__device__ __forceinline__ unsigned su(const void* p) {
    return (unsigned)__cvta_generic_to_shared(p);
}
__device__ __forceinline__ void cpa16(void* dst, const void* src) {
    asm volatile("cp.async.cg.shared.global [%0], [%1], 16;" :: "r"(su(dst)), "l"(src));
}
#define CP_COMMIT() asm volatile("cp.async.commit_group;")
#define CP_WAIT1()  asm volatile("cp.async.wait_group 1;")
#define CP_WAIT0()  asm volatile("cp.async.wait_group 0;")

// step smem: 3 stages x 2 arrays x {A: 64xLDA, B: 128xLDB}
#define SMEM_STEP (6*64*LDA*2 + 6*128*LDB*2)   // 165888 B
#define SMEM_OUT  ((2*64*LDA + 2*64*LDB) * 2)  // 36864 B
extern __shared__ __half smh[];

__device__ __forceinline__ void load_afrag(unsigned* f, const __half* A, int rbase) {
    f[0] = *(const unsigned*)(A + rbase);
    f[1] = *(const unsigned*)(A + rbase + 8 * LDA);
    f[2] = *(const unsigned*)(A + rbase + 8);
    f[3] = *(const unsigned*)(A + rbase + 8 * LDA + 8);
}

// ---------------- utility kernels ----------------
__global__ void k_split(const float* __restrict__ s, __half* __restrict__ d1,
                        __half* __restrict__ d2, int n) {
    int i = blockIdx.x * blockDim.x + threadIdx.x;
    for (; i < n; i += gridDim.x * blockDim.x) {
        float v = s[i];
        __half h1 = __float2half_rn(v);
        d1[i] = h1;
        d2[i] = __float2half_rn(v - __half2float(h1));
    }
}
__global__ void k_zero_state() {   // zero both dirs, both parities
    int i = blockIdx.x * blockDim.x + threadIdx.x;
    if (i < 2 * Bz * Hz) {
        __half zz = __float2half(0.f);
        g_h1[0][i] = zz; g_h1[1][i] = zz; g_h2[0][i] = zz; g_h2[1][i] = zz; g_c[i] = 0.f;
    }
}
__global__ void k_hd_init() {
    int i = blockIdx.x * blockDim.x + threadIdx.x;
    if (i < Bz * Hz) {
        float v = g_htmp[i];
        __half h1 = __float2half_rn(v);
        g_h1[0][i] = h1;
        g_h2[0][i] = __float2half_rn(v - __half2float(h1));
        g_c[i] = 0.f;
    }
}
__global__ void k_copy_hcat() {    // both halves in one launch
    int i = blockIdx.x * blockDim.x + threadIdx.x;
    if (i < 2 * Bz * Hz) {
        int s = i >> 9;                 // state row 0..1023
        int j = i & (Hz - 1);
        int b = s & (Bz - 1);
        int dir = s >> 9;
        g_hcat[b * (2 * Hz) + dir * Hz + j] =
            __half2float(g_h1[0][i]) + __half2float(g_h2[0][i]);
    }
}
__global__ void k_reparam(const float* __restrict__ eps, const float* __restrict__ muv,
                          const float* __restrict__ lvv) {
    int i = blockIdx.x * blockDim.x + threadIdx.x;
    if (i < Bz * Lz) g_z[i] = muv[i] + eps[i] * expf(0.5f * lvv[i]);
}

// ---------------- fp32 GEMM: C[M,N] = A[M,K]@Bw[N,K]^T (+bias) ----------------
__global__ __launch_bounds__(256) void k_gemm(int K,
                                              const float* __restrict__ A, int lda,
                                              const float* __restrict__ Bw, int ldb,
                                              const float* __restrict__ bias,
                                              float* __restrict__ C, int ldc) {
    __shared__ float As[16][68];
    __shared__ float Bs[16][68];
    const int tid = threadIdx.x;
    const int m0 = blockIdx.y * 64, n0 = blockIdx.x * 64;
    const int lr = tid >> 2, lk = tid & 3;
    const int tx = tid & 15, ty = tid >> 4;
    float acc[4][4] = {};
    for (int k0 = 0; k0 < K; k0 += 16) {
        float4 av = *(const float4*)(A + (size_t)(m0 + lr) * lda + k0 + lk * 4);
        float4 bv = *(const float4*)(Bw + (size_t)(n0 + lr) * ldb + k0 + lk * 4);
        __syncthreads();
        As[lk*4+0][lr]=av.x; As[lk*4+1][lr]=av.y; As[lk*4+2][lr]=av.z; As[lk*4+3][lr]=av.w;
        Bs[lk*4+0][lr]=bv.x; Bs[lk*4+1][lr]=bv.y; Bs[lk*4+2][lr]=bv.z; Bs[lk*4+3][lr]=bv.w;
        __syncthreads();
#pragma unroll
        for (int k = 0; k < 16; k++) {
            float4 a = *(const float4*)&As[k][ty*4];
            float4 b = *(const float4*)&Bs[k][tx*4];
            acc[0][0]+=a.x*b.x; acc[0][1]+=a.x*b.y; acc[0][2]+=a.x*b.z; acc[0][3]+=a.x*b.w;
            acc[1][0]+=a.y*b.x; acc[1][1]+=a.y*b.y; acc[1][2]+=a.y*b.z; acc[1][3]+=a.y*b.w;
            acc[2][0]+=a.z*b.x; acc[2][1]+=a.z*b.y; acc[2][2]+=a.z*b.z; acc[2][3]+=a.z*b.w;
            acc[3][0]+=a.w*b.x; acc[3][1]+=a.w*b.y; acc[3][2]+=a.w*b.z; acc[3][3]+=a.w*b.w;
        }
    }
#pragma unroll
    for (int i = 0; i < 4; i++)
#pragma unroll
        for (int j = 0; j < 4; j++) {
            int n = n0 + tx * 4 + j;
            float bb = bias ? bias[n] : 0.0f;
            C[(size_t)(m0 + ty * 4 + i) * ldc + n] = acc[i][j] + bb;
        }
}

// ---------------- fused LSTM step, split-fp16 3-MMA, 3-stage cp.async ----------------
// CTA: 64 batch x 128 gate-cols (4 gates x 32 j). 512 threads, 16 warps (4m x 4n).
// Encoder: grid (16, 16) — blockIdx.y>>3 selects direction (0=fwd, 1=bwd).
// Decoder: grid (16, 8) — dir always 0; pass same ptrs for both dir slots.
__global__ __launch_bounds__(512) void k_steph(int t, int pin,
                                               const __half* __restrict__ U1a,
                                               const __half* __restrict__ U2a,
                                               const __half* __restrict__ U1b,
                                               const __half* __restrict__ U2b,
                                               const int* __restrict__ ids,
                                               const float* __restrict__ Ea,
                                               const float* __restrict__ Eb,
                                               int use_zp, int store_hs) {
    __shared__ int toks[64];
    const int tid = threadIdx.x;
    const int by = blockIdx.y;
    const int dir = by >> 3;
    const int b0 = (by & 7) * 64;           // batch base (token row)
    const int sb0 = dir * Bz + b0;          // state base row
    const int j0 = blockIdx.x * 32;
    const __half* U1 = dir ? U1b : U1a;
    const __half* U2 = dir ? U2b : U2a;
    const float*  E  = dir ? Eb  : Ea;
    const __half* h1 = g_h1[pin];
    const __half* h2 = g_h2[pin];
    const int lane = tid & 31, warp = tid >> 5;
    const int wm = warp >> 2, wn = warp & 3;
    const int g = lane >> 2, i2 = (lane & 3) * 2;

    if (tid < 64) {
        int tt = dir ? (Tz - 1 - t) : t;
        toks[tid] = ids[(b0 + tid) * Tz + tt];
    }

    __half* Abase = smh;                 // [stage][arr][64][LDA]
    __half* Bbase = smh + 6 * 64 * LDA;  // [stage][arr][128][LDB]
#define A_ST(st, arr) (Abase + ((st)*2 + (arr)) * 64 * LDA)
#define B_ST(st, arr) (Bbase + ((st)*2 + (arr)) * 128 * LDB)

    auto stage_load = [&](int st, int k0) {
        {
            int r = tid >> 3, col = (tid & 7) * 8;
            const size_t off = (size_t)(sb0 + r) * Hz + k0 + col;
            cpa16(A_ST(st, 0) + r * LDA + col, h1 + off);
            cpa16(A_ST(st, 1) + r * LDA + col, h2 + off);
        }
#pragma unroll
        for (int it = 0; it < 2; it++) {
            int c = tid + it * 512, r = c >> 3, col = (c & 7) * 8;
            int q = (r >> 3) & 3, wnr = r >> 5, s = r & 7;
            size_t goff = (size_t)(q * Hz + j0 + wnr * 8 + s) * Hz + k0 + col;
            cpa16(B_ST(st, 0) + r * LDB + col, U1 + goff);
            cpa16(B_ST(st, 1) + r * LDB + col, U2 + goff);
        }
    };

    float acc[4][4] = {};
    stage_load(0, 0);   CP_COMMIT();
    stage_load(1, 64);  CP_COMMIT();

    for (int kc = 0; kc < 8; kc++) {
        if (kc == 7) { CP_WAIT0(); } else { CP_WAIT1(); }
        __syncthreads();
        if (kc < 6) {                       // prefetch distance 2
            stage_load((kc + 2) % 3, (kc + 2) * 64);
            CP_COMMIT();
        }
        const int st = kc % 3;
        const __half* A1 = A_ST(st, 0);
        const __half* A2 = A_ST(st, 1);
        const __half* B1 = B_ST(st, 0);
        const __half* B2 = B_ST(st, 1);
#pragma unroll
        for (int kk = 0; kk < 4; kk++) {
            int k = kk * 16;
            unsigned a1f[4], a2f[4], b1f[4][2], b2f[4][2];
            int rbase = (wm * 16 + g) * LDA + k + i2;
            load_afrag(a1f, A1, rbase);
            load_afrag(a2f, A2, rbase);
#pragma unroll
            for (int q = 0; q < 4; q++) {
                int rb = (wn * 32 + q * 8 + g) * LDB + k + i2;
                b1f[q][0] = *(const unsigned*)(B1 + rb);
                b1f[q][1] = *(const unsigned*)(B1 + rb + 8);
                b2f[q][0] = *(const unsigned*)(B2 + rb);
                b2f[q][1] = *(const unsigned*)(B2 + rb + 8);
            }
#pragma unroll
            for (int q = 0; q < 4; q++) {
                mma16816(acc[q], a1f, b1f[q][0], b1f[q][1]);
                mma16816(acc[q], a1f, b2f[q][0], b2f[q][1]);
                mma16816(acc[q], a2f, b1f[q][0], b1f[q][1]);
            }
        }
    }

    // epilogue: gather E (+zp), gates, state update
    __half* o1 = g_h1[pin ^ 1];
    __half* o2 = g_h2[pin ^ 1];
    const int jb = j0 + wn * 8 + i2;
#pragma unroll
    for (int rs = 0; rs < 2; rs++) {
        int r = wm * 16 + g + rs * 8;
        int b = b0 + r;                     // token/batch row
        int sb = sb0 + r;                   // state row
        int tok = toks[r];
        float2 gv[4];
#pragma unroll
        for (int q = 0; q < 4; q++) {
            int n = q * Hz + jb;
            float2 e = *(const float2*)&E[(size_t)tok * G4z + n];
            if (use_zp) {
                float2 zp2 = *(const float2*)&g_zp[(size_t)b * G4z + n];
                e.x += zp2.x; e.y += zp2.y;
            }
            gv[q] = make_float2(acc[q][rs * 2 + 0] + e.x, acc[q][rs * 2 + 1] + e.y);
        }
        int idx = sb * Hz + jb;
        float2 cold = *(const float2*)&g_c[idx];
        float cn0 = sigm(gv[1].x) * cold.x + sigm(gv[0].x) * tanhf(gv[2].x);
        float cn1 = sigm(gv[1].y) * cold.y + sigm(gv[0].y) * tanhf(gv[2].y);
        float hn0 = sigm(gv[3].x) * tanhf(cn0);
        float hn1 = sigm(gv[3].y) * tanhf(cn1);
        *(float2*)&g_c[idx] = make_float2(cn0, cn1);
        __half p0 = __float2half_rn(hn0), p1 = __float2half_rn(hn1);
        __half q0 = __float2half_rn(hn0 - __half2float(p0));
        __half q1 = __float2half_rn(hn1 - __half2float(p1));
        *(__half2*)&o1[idx] = __halves2half2(p0, p1);
        *(__half2*)&o2[idx] = __halves2half2(q0, q1);
        if (store_hs) {
            size_t hi = ((size_t)t * Bz + b) * Hz + jb;
            *(__half2*)&g_hs1[hi] = __halves2half2(p0, p1);
            *(__half2*)&g_hs2[hi] = __halves2half2(q0, q1);
        }
    }
}

// ---------------- output head: out[b][t][v] = hs[m]@Wout^T + b_out ----------------
__global__ __launch_bounds__(256) void k_outheadh(const float* __restrict__ bout,
                                                  float* __restrict__ out) {
    __half* A1 = smh;
    __half* A2 = smh + 64 * LDA;
    __half* B1 = smh + 2 * 64 * LDA;
    __half* B2 = smh + 2 * 64 * LDA + 64 * LDB;
    const int tid = threadIdx.x;
    const int m0 = blockIdx.x * 64;
    const int lane = tid & 31, warp = tid >> 5;
    const int wm = warp >> 2, wn = warp & 3;
    const int g = lane >> 2, i2 = (lane & 3) * 2;
    float acc[2][2][4] = {};

    for (int kc = 0; kc < 8; kc++) {
        int k0 = kc * 64;
        __syncthreads();
#pragma unroll
        for (int it = 0; it < 2; it++) {
            int c = tid + it * 256, r = c >> 3, col = (c & 7) * 8;
            *(uint4*)(A1 + r * LDA + col) = *(const uint4*)(g_hs1 + (size_t)(m0 + r) * Hz + k0 + col);
            *(uint4*)(A2 + r * LDA + col) = *(const uint4*)(g_hs2 + (size_t)(m0 + r) * Hz + k0 + col);
            *(uint4*)(B1 + r * LDB + col) = *(const uint4*)(g_Wo1 + (size_t)r * Hz + k0 + col);
            *(uint4*)(B2 + r * LDB + col) = *(const uint4*)(g_Wo2 + (size_t)r * Hz + k0 + col);
        }
        __syncthreads();
#pragma unroll
        for (int kk = 0; kk < 4; kk++) {
            int k = kk * 16;
            unsigned a1f[2][4], a2f[2][4], b1f[2][2], b2f[2][2];
#pragma unroll
            for (int mt = 0; mt < 2; mt++) {
                int rbase = (wm * 32 + mt * 16 + g) * LDA + k + i2;
                load_afrag(a1f[mt], A1, rbase);
                load_afrag(a2f[mt], A2, rbase);
            }
#pragma unroll
            for (int nt = 0; nt < 2; nt++) {
                int rb = (wn * 16 + nt * 8 + g) * LDB + k + i2;
                b1f[nt][0] = *(const unsigned*)(B1 + rb);
                b1f[nt][1] = *(const unsigned*)(B1 + rb + 8);
                b2f[nt][0] = *(const unsigned*)(B2 + rb);
                b2f[nt][1] = *(const unsigned*)(B2 + rb + 8);
            }
#pragma unroll
            for (int mt = 0; mt < 2; mt++)
#pragma unroll
                for (int nt = 0; nt < 2; nt++) {
                    mma16816(acc[mt][nt], a1f[mt], b1f[nt][0], b1f[nt][1]);
                    mma16816(acc[mt][nt], a1f[mt], b2f[nt][0], b2f[nt][1]);
                    mma16816(acc[mt][nt], a2f[mt], b1f[nt][0], b1f[nt][1]);
                }
        }
    }
#pragma unroll
    for (int mt = 0; mt < 2; mt++)
#pragma unroll
        for (int rs = 0; rs < 2; rs++)
#pragma unroll
            for (int jj = 0; jj < 2; jj++) {
                int m = m0 + wm * 32 + mt * 16 + g + rs * 8;
                int b = m & (Bz - 1), tt = m >> 9;
                int ci = rs * 2 + jj;
#pragma unroll
                for (int nt = 0; nt < 2; nt++) {
                    int v = wn * 16 + nt * 8 + i2 + jj;
                    out[((size_t)b * Tz + tt) * Vz + v] = acc[mt][nt][ci] + bout[v];
                }
            }
}

// ---------------- launch ----------------
extern "C" void kernel_launch(void* const* d_in, const int* in_sizes, int n_in,
                              void* d_out, int out_size) {
    const int* x   = (const int*)d_in[0];
    const int* tgt = (const int*)d_in[1];
    const float* eps   = (const float*)d_in[2];
    const float* emb   = (const float*)d_in[3];
    const float* Wih_f = (const float*)d_in[4];
    const float* Whh_f = (const float*)d_in[5];
    const float* b_f   = (const float*)d_in[6];
    const float* Wih_b = (const float*)d_in[7];
    const float* Whh_b = (const float*)d_in[8];
    const float* b_b   = (const float*)d_in[9];
    const float* W_mu  = (const float*)d_in[10];
    const float* b_mu  = (const float*)d_in[11];
    const float* W_lv  = (const float*)d_in[12];
    const float* b_lv  = (const float*)d_in[13];
    const float* W_di  = (const float*)d_in[14];
    const float* b_di  = (const float*)d_in[15];
    const float* Wih_d = (const float*)d_in[16];
    const float* Whh_d = (const float*)d_in[17];
    const float* b_d   = (const float*)d_in[18];
    const float* W_out = (const float*)d_in[19];
    const float* b_out = (const float*)d_in[20];

    float* out  = (float*)d_out;
    float* mu_o = out + (size_t)Bz * Tz * Vz;
    float* lv_o = mu_o + Bz * Lz;

    cudaFuncSetAttribute(k_steph,    cudaFuncAttributeMaxDynamicSharedMemorySize, SMEM_STEP);
    cudaFuncSetAttribute(k_outheadh, cudaFuncAttributeMaxDynamicSharedMemorySize, SMEM_OUT);

    __half *uf1, *uf2, *ub1, *ub2, *ud1, *ud2, *wo1, *wo2;
    float *ef, *eb, *ed, *hcat, *z, *zp, *htmp;
    cudaGetSymbolAddress((void**)&uf1, g_Uf1); cudaGetSymbolAddress((void**)&uf2, g_Uf2);
    cudaGetSymbolAddress((void**)&ub1, g_Ub1); cudaGetSymbolAddress((void**)&ub2, g_Ub2);
    cudaGetSymbolAddress((void**)&ud1, g_Ud1); cudaGetSymbolAddress((void**)&ud2, g_Ud2);
    cudaGetSymbolAddress((void**)&wo1, g_Wo1); cudaGetSymbolAddress((void**)&wo2, g_Wo2);
    cudaGetSymbolAddress((void**)&ef, g_EF);   cudaGetSymbolAddress((void**)&eb, g_EB);
    cudaGetSymbolAddress((void**)&ed, g_ED);
    cudaGetSymbolAddress((void**)&hcat, g_hcat);
    cudaGetSymbolAddress((void**)&z, g_z);
    cudaGetSymbolAddress((void**)&zp, g_zp);
    cudaGetSymbolAddress((void**)&htmp, g_htmp);

    k_split<<<512, 256>>>(Whh_f, uf1, uf2, G4z * Hz);
    k_split<<<512, 256>>>(Whh_b, ub1, ub2, G4z * Hz);
    k_split<<<512, 256>>>(Whh_d, ud1, ud2, G4z * Hz);
    k_split<<<64, 256>>>(W_out, wo1, wo2, Vz * Hz);

    // embedding projection tables (fp32): E = emb @ Wih^T + b   (M=64, N=2048)
    k_gemm<<<dim3(32, 1), 256>>>(Ez, emb, Ez, Wih_f, Ez, b_f, ef, G4z);
    k_gemm<<<dim3(32, 1), 256>>>(Ez, emb, Ez, Wih_b, Ez, b_b, eb, G4z);
    k_gemm<<<dim3(32, 1), 256>>>(Ez, emb, Ez, Wih_d, ELz, b_d, ed, G4z);

    dim3 encGrid(Hz / 32, 16);   // (16, 16): both directions
    dim3 decGrid(Hz / 32, 8);    // (16, 8)
    int zeroBlocks2 = (2 * Bz * Hz + 255) / 256;
    int zeroBlocks1 = (Bz * Hz + 255) / 256;

    // ---- encoder (both directions fused) ----
    k_zero_state<<<zeroBlocks2, 256>>>();
    for (int t = 0; t < Tz; t++)
        k_steph<<<encGrid, 512, SMEM_STEP>>>(t, t & 1, uf1, uf2, ub1, ub2, x, ef, eb, 0, 0);
    k_copy_hcat<<<zeroBlocks2, 256>>>();

    // ---- latent heads + reparameterize (fp32) ----
    k_gemm<<<dim3(Lz / 64, Bz / 64), 256>>>(2 * Hz, hcat, 2 * Hz, W_mu, 2 * Hz, b_mu, mu_o, Lz);
    k_gemm<<<dim3(Lz / 64, Bz / 64), 256>>>(2 * Hz, hcat, 2 * Hz, W_lv, 2 * Hz, b_lv, lv_o, Lz);
    k_reparam<<<(Bz * Lz + 255) / 256, 256>>>(eps, mu_o, lv_o);

    // ---- decoder prologue ----
    k_gemm<<<dim3(G4z / 64, Bz / 64), 256>>>(Lz, z, Lz, Wih_d + Ez, ELz, nullptr, zp, G4z);
    k_gemm<<<dim3(Hz / 64, Bz / 64), 256>>>(Lz, z, Lz, W_di, Lz, b_di, htmp, Hz);
    k_hd_init<<<zeroBlocks1, 256>>>();

    // ---- decoder recurrence ----
    for (int t = 0; t < Tz; t++)
        k_steph<<<decGrid, 512, SMEM_STEP>>>(t, t & 1, ud1, ud2, ud1, ud2, tgt, ed, ed, 1, 1);

    // ---- output head ----
    k_outheadh<<<(Tz * Bz) / 64, 256, SMEM_OUT>>>(b_out, out);
}

// round 7
// speedup vs baseline: 4.3904x; 1.0993x over previous
#include <cuda_runtime.h>
#include <cuda_fp16.h>
#include <math.h>

#define Bz 512
#define Tz 128
#define Vz 64
#define Ez 256
#define Hz 512
#define Lz 128
#define G4z 2048
#define ELz 384
#define LDA 72
#define LDB 72

// ---------------- scratch ----------------
__device__ __align__(16) __half g_h1[2][2 * Bz * Hz];
__device__ __align__(16) __half g_h2[2][2 * Bz * Hz];
__device__ __align__(16) float  g_c[2 * Bz * Hz];
__device__ __align__(16) float  g_htmp[Bz * Hz];
__device__ __align__(16) float  g_hcat[Bz * 2 * Hz];
__device__ __align__(16) float  g_z[Bz * Lz];
__device__ __align__(16) float  g_zp[Bz * G4z];
__device__ __align__(16) __half g_hs1[(size_t)Tz * Bz * Hz];
__device__ __align__(16) __half g_hs2[(size_t)Tz * Bz * Hz];
__device__ __align__(16) float  g_EF[Vz * G4z];
__device__ __align__(16) float  g_EB[Vz * G4z];
__device__ __align__(16) float  g_ED[Vz * G4z];
__device__ __align__(16) __half g_Uf1[G4z * Hz], g_Uf2[G4z * Hz];
__device__ __align__(16) __half g_Ub1[G4z * Hz], g_Ub2[G4z * Hz];
__device__ __align__(16) __half g_Ud1[G4z * Hz], g_Ud2[G4z * Hz];
__device__ __align__(16) __half g_Wo1[Vz * Hz],  g_Wo2[Vz * Hz];

__device__ __forceinline__ float sigm(float x) { return 1.0f / (1.0f + expf(-x)); }

__device__ __forceinline__ void mma16816(float* d, const unsigned* a, unsigned b0, unsigned b1) {
    asm volatile("mma.sync.aligned.m16n8k16.row.col.f32.f16.f16.f32 "
                 "{%0,%1,%2,%3},{%4,%5,%6,%7},{%8,%9},{%0,%1,%2,%3};"
                 : "+f"(d[0]), "+f"(d[1]), "+f"(d[2]), "+f"(d[3])
                 : "r"(a[0]), "r"(a[1]), "r"(a[2]), "r"(a[3]), "r"(b0), "r"(b1));
}
__device__ __forceinline__ unsigned su(const void* p) {
    return (unsigned)__cvta_generic_to_shared(p);
}
__device__ __forceinline__ void cpa16(void* dst, const void* src) {
    asm volatile("cp.async.cg.shared.global [%0], [%1], 16;" :: "r"(su(dst)), "l"(src));
}
#define CP_COMMIT() asm volatile("cp.async.commit_group;")
#define CP_WAIT1()  asm volatile("cp.async.wait_group 1;")
#define CP_WAIT0()  asm volatile("cp.async.wait_group 0;")

#define SMEM_STEP  (6*64*LDA*2 + 6*128*LDB*2)    // decoder: 3 stages  (165888 B)
#define SMEM_STEP2 (4*128*LDA*2 + 4*128*LDB*2)   // encoder BM=128: 2 stages (147456 B)
#define SMEM_OUT   ((2*64*LDA + 2*64*LDB) * 2)
extern __shared__ __half smh[];

__device__ __forceinline__ void load_afrag(unsigned* f, const __half* A, int rbase) {
    f[0] = *(const unsigned*)(A + rbase);
    f[1] = *(const unsigned*)(A + rbase + 8 * LDA);
    f[2] = *(const unsigned*)(A + rbase + 8);
    f[3] = *(const unsigned*)(A + rbase + 8 * LDA + 8);
}

// ---------------- utility kernels ----------------
__global__ void k_split(const float* __restrict__ s, __half* __restrict__ d1,
                        __half* __restrict__ d2, int n) {
    int i = blockIdx.x * blockDim.x + threadIdx.x;
    for (; i < n; i += gridDim.x * blockDim.x) {
        float v = s[i];
        __half h1 = __float2half_rn(v);
        d1[i] = h1;
        d2[i] = __float2half_rn(v - __half2float(h1));
    }
}
__global__ void k_zero_state() {
    int i = blockIdx.x * blockDim.x + threadIdx.x;
    if (i < 2 * Bz * Hz) {
        __half zz = __float2half(0.f);
        g_h1[0][i] = zz; g_h1[1][i] = zz; g_h2[0][i] = zz; g_h2[1][i] = zz; g_c[i] = 0.f;
    }
}
__global__ void k_hd_init() {
    int i = blockIdx.x * blockDim.x + threadIdx.x;
    if (i < Bz * Hz) {
        float v = g_htmp[i];
        __half h1 = __float2half_rn(v);
        g_h1[0][i] = h1;
        g_h2[0][i] = __float2half_rn(v - __half2float(h1));
        g_c[i] = 0.f;
    }
}
__global__ void k_copy_hcat() {
    int i = blockIdx.x * blockDim.x + threadIdx.x;
    if (i < 2 * Bz * Hz) {
        int s = i >> 9;
        int j = i & (Hz - 1);
        int b = s & (Bz - 1);
        int dir = s >> 9;
        g_hcat[b * (2 * Hz) + dir * Hz + j] =
            __half2float(g_h1[0][i]) + __half2float(g_h2[0][i]);
    }
}
__global__ void k_reparam(const float* __restrict__ eps, const float* __restrict__ muv,
                          const float* __restrict__ lvv) {
    int i = blockIdx.x * blockDim.x + threadIdx.x;
    if (i < Bz * Lz) g_z[i] = muv[i] + eps[i] * expf(0.5f * lvv[i]);
}

// ---------------- fp32 GEMM ----------------
__global__ __launch_bounds__(256) void k_gemm(int K,
                                              const float* __restrict__ A, int lda,
                                              const float* __restrict__ Bw, int ldb,
                                              const float* __restrict__ bias,
                                              float* __restrict__ C, int ldc) {
    __shared__ float As[16][68];
    __shared__ float Bs[16][68];
    const int tid = threadIdx.x;
    const int m0 = blockIdx.y * 64, n0 = blockIdx.x * 64;
    const int lr = tid >> 2, lk = tid & 3;
    const int tx = tid & 15, ty = tid >> 4;
    float acc[4][4] = {};
    for (int k0 = 0; k0 < K; k0 += 16) {
        float4 av = *(const float4*)(A + (size_t)(m0 + lr) * lda + k0 + lk * 4);
        float4 bv = *(const float4*)(Bw + (size_t)(n0 + lr) * ldb + k0 + lk * 4);
        __syncthreads();
        As[lk*4+0][lr]=av.x; As[lk*4+1][lr]=av.y; As[lk*4+2][lr]=av.z; As[lk*4+3][lr]=av.w;
        Bs[lk*4+0][lr]=bv.x; Bs[lk*4+1][lr]=bv.y; Bs[lk*4+2][lr]=bv.z; Bs[lk*4+3][lr]=bv.w;
        __syncthreads();
#pragma unroll
        for (int k = 0; k < 16; k++) {
            float4 a = *(const float4*)&As[k][ty*4];
            float4 b = *(const float4*)&Bs[k][tx*4];
            acc[0][0]+=a.x*b.x; acc[0][1]+=a.x*b.y; acc[0][2]+=a.x*b.z; acc[0][3]+=a.x*b.w;
            acc[1][0]+=a.y*b.x; acc[1][1]+=a.y*b.y; acc[1][2]+=a.y*b.z; acc[1][3]+=a.y*b.w;
            acc[2][0]+=a.z*b.x; acc[2][1]+=a.z*b.y; acc[2][2]+=a.z*b.z; acc[2][3]+=a.z*b.w;
            acc[3][0]+=a.w*b.x; acc[3][1]+=a.w*b.y; acc[3][2]+=a.w*b.z; acc[3][3]+=a.w*b.w;
        }
    }
#pragma unroll
    for (int i = 0; i < 4; i++)
#pragma unroll
        for (int j = 0; j < 4; j++) {
            int n = n0 + tx * 4 + j;
            float bb = bias ? bias[n] : 0.0f;
            C[(size_t)(m0 + ty * 4 + i) * ldc + n] = acc[i][j] + bb;
        }
}

// ---------------- decoder step (R6-proven): BM=64, 3-stage ----------------
__global__ __launch_bounds__(512) void k_steph(int t, int pin,
                                               const __half* __restrict__ U1,
                                               const __half* __restrict__ U2,
                                               const int* __restrict__ ids,
                                               const float* __restrict__ E,
                                               int use_zp, int store_hs) {
    __shared__ int toks[64];
    const int tid = threadIdx.x;
    const int b0 = blockIdx.y * 64;
    const int j0 = blockIdx.x * 32;
    const __half* h1 = g_h1[pin];
    const __half* h2 = g_h2[pin];
    const int lane = tid & 31, warp = tid >> 5;
    const int wm = warp >> 2, wn = warp & 3;
    const int g = lane >> 2, i2 = (lane & 3) * 2;

    if (tid < 64) toks[tid] = ids[(b0 + tid) * Tz + t];

    __half* Abase = smh;
    __half* Bbase = smh + 6 * 64 * LDA;
#define A_ST(st, arr) (Abase + ((st)*2 + (arr)) * 64 * LDA)
#define B_ST(st, arr) (Bbase + ((st)*2 + (arr)) * 128 * LDB)

    auto stage_load = [&](int st, int k0) {
        {
            int r = tid >> 3, col = (tid & 7) * 8;
            const size_t off = (size_t)(b0 + r) * Hz + k0 + col;
            cpa16(A_ST(st, 0) + r * LDA + col, h1 + off);
            cpa16(A_ST(st, 1) + r * LDA + col, h2 + off);
        }
#pragma unroll
        for (int it = 0; it < 2; it++) {
            int c = tid + it * 512, r = c >> 3, col = (c & 7) * 8;
            int q = (r >> 3) & 3, wnr = r >> 5, s = r & 7;
            size_t goff = (size_t)(q * Hz + j0 + wnr * 8 + s) * Hz + k0 + col;
            cpa16(B_ST(st, 0) + r * LDB + col, U1 + goff);
            cpa16(B_ST(st, 1) + r * LDB + col, U2 + goff);
        }
    };

    float acc[4][4] = {};
    stage_load(0, 0);   CP_COMMIT();
    stage_load(1, 64);  CP_COMMIT();

    for (int kc = 0; kc < 8; kc++) {
        if (kc == 7) { CP_WAIT0(); } else { CP_WAIT1(); }
        __syncthreads();
        if (kc < 6) {
            stage_load((kc + 2) % 3, (kc + 2) * 64);
            CP_COMMIT();
        }
        const int st = kc % 3;
        const __half* A1 = A_ST(st, 0);
        const __half* A2 = A_ST(st, 1);
        const __half* B1 = B_ST(st, 0);
        const __half* B2 = B_ST(st, 1);
#pragma unroll
        for (int kk = 0; kk < 4; kk++) {
            int k = kk * 16;
            unsigned a1f[4], a2f[4], b1f[4][2], b2f[4][2];
            int rbase = (wm * 16 + g) * LDA + k + i2;
            load_afrag(a1f, A1, rbase);
            load_afrag(a2f, A2, rbase);
#pragma unroll
            for (int q = 0; q < 4; q++) {
                int rb = (wn * 32 + q * 8 + g) * LDB + k + i2;
                b1f[q][0] = *(const unsigned*)(B1 + rb);
                b1f[q][1] = *(const unsigned*)(B1 + rb + 8);
                b2f[q][0] = *(const unsigned*)(B2 + rb);
                b2f[q][1] = *(const unsigned*)(B2 + rb + 8);
            }
#pragma unroll
            for (int q = 0; q < 4; q++) {
                mma16816(acc[q], a1f, b1f[q][0], b1f[q][1]);
                mma16816(acc[q], a1f, b2f[q][0], b2f[q][1]);
                mma16816(acc[q], a2f, b1f[q][0], b1f[q][1]);
            }
        }
    }

    __half* o1 = g_h1[pin ^ 1];
    __half* o2 = g_h2[pin ^ 1];
    const int jb = j0 + wn * 8 + i2;
#pragma unroll
    for (int rs = 0; rs < 2; rs++) {
        int r = wm * 16 + g + rs * 8;
        int b = b0 + r;
        int tok = toks[r];
        float2 gv[4];
#pragma unroll
        for (int q = 0; q < 4; q++) {
            int n = q * Hz + jb;
            float2 e = *(const float2*)&E[(size_t)tok * G4z + n];
            if (use_zp) {
                float2 zp2 = *(const float2*)&g_zp[(size_t)b * G4z + n];
                e.x += zp2.x; e.y += zp2.y;
            }
            gv[q] = make_float2(acc[q][rs * 2 + 0] + e.x, acc[q][rs * 2 + 1] + e.y);
        }
        int idx = b * Hz + jb;
        float2 cold = *(const float2*)&g_c[idx];
        float cn0 = sigm(gv[1].x) * cold.x + sigm(gv[0].x) * tanhf(gv[2].x);
        float cn1 = sigm(gv[1].y) * cold.y + sigm(gv[0].y) * tanhf(gv[2].y);
        float hn0 = sigm(gv[3].x) * tanhf(cn0);
        float hn1 = sigm(gv[3].y) * tanhf(cn1);
        *(float2*)&g_c[idx] = make_float2(cn0, cn1);
        __half p0 = __float2half_rn(hn0), p1 = __float2half_rn(hn1);
        __half q0 = __float2half_rn(hn0 - __half2float(p0));
        __half q1 = __float2half_rn(hn1 - __half2float(p1));
        *(__half2*)&o1[idx] = __halves2half2(p0, p1);
        *(__half2*)&o2[idx] = __halves2half2(q0, q1);
        if (store_hs) {
            size_t hi = ((size_t)t * Bz + b) * Hz + jb;
            *(__half2*)&g_hs1[hi] = __halves2half2(p0, p1);
            *(__half2*)&g_hs2[hi] = __halves2half2(q0, q1);
        }
    }
#undef A_ST
#undef B_ST
}

// ---------------- encoder step: BM=128 (both dirs), 2-stage, 1 wave ----------------
// grid (16, 8): by>>2 = dir, (by&3)*128 = batch base. 512 threads, 16 warps (4m x 4n),
// warp tile 32m x 32n (4 gates x 8 j).
__global__ __launch_bounds__(512) void k_steph2(int t, int pin,
                                                const __half* __restrict__ U1a,
                                                const __half* __restrict__ U2a,
                                                const __half* __restrict__ U1b,
                                                const __half* __restrict__ U2b,
                                                const int* __restrict__ ids,
                                                const float* __restrict__ Ea,
                                                const float* __restrict__ Eb) {
    __shared__ int toks[128];
    const int tid = threadIdx.x;
    const int by = blockIdx.y;
    const int dir = by >> 2;
    const int b0 = (by & 3) * 128;
    const int sb0 = dir * Bz + b0;
    const int j0 = blockIdx.x * 32;
    const __half* U1 = dir ? U1b : U1a;
    const __half* U2 = dir ? U2b : U2a;
    const float*  E  = dir ? Eb  : Ea;
    const __half* h1 = g_h1[pin];
    const __half* h2 = g_h2[pin];
    const int lane = tid & 31, warp = tid >> 5;
    const int wm = warp >> 2, wn = warp & 3;
    const int g = lane >> 2, i2 = (lane & 3) * 2;

    if (tid < 128) {
        int tt = dir ? (Tz - 1 - t) : t;
        toks[tid] = ids[(b0 + tid) * Tz + tt];
    }

    __half* Abase = smh;                  // [stage][arr][128][LDA]
    __half* Bbase = smh + 4 * 128 * LDA;  // [stage][arr][128][LDB]
#define A2_ST(st, arr) (Abase + ((st)*2 + (arr)) * 128 * LDA)
#define B2_ST(st, arr) (Bbase + ((st)*2 + (arr)) * 128 * LDB)

    auto stage_load = [&](int st, int k0) {
#pragma unroll
        for (int it = 0; it < 4; it++) {
            int c = tid + it * 512;
            int arr = c >> 10, rr = c & 1023;
            int r = rr >> 3, col = (rr & 7) * 8;
            const __half* hp = arr ? h2 : h1;
            cpa16(A2_ST(st, arr) + r * LDA + col, hp + (size_t)(sb0 + r) * Hz + k0 + col);
        }
#pragma unroll
        for (int it = 0; it < 4; it++) {
            int c = tid + it * 512;
            int arr = c >> 10, rr = c & 1023;
            int r = rr >> 3, col = (rr & 7) * 8;
            int q = (r >> 3) & 3, wnr = r >> 5, s = r & 7;
            const __half* Up = arr ? U2 : U1;
            size_t goff = (size_t)(q * Hz + j0 + wnr * 8 + s) * Hz + k0 + col;
            cpa16(B2_ST(st, arr) + r * LDB + col, Up + goff);
        }
    };

    float acc[2][4][4] = {};
    stage_load(0, 0);
    CP_COMMIT();

    for (int kc = 0; kc < 8; kc++) {
        CP_WAIT0();
        __syncthreads();               // stage kc ready; stage (kc+1)&1 fully drained
        if (kc < 7) {
            stage_load((kc + 1) & 1, (kc + 1) * 64);
            CP_COMMIT();
        }
        const __half* A1 = A2_ST(kc & 1, 0);
        const __half* A2 = A2_ST(kc & 1, 1);
        const __half* B1 = B2_ST(kc & 1, 0);
        const __half* B2 = B2_ST(kc & 1, 1);
#pragma unroll
        for (int kk = 0; kk < 4; kk++) {
            int k = kk * 16;
            unsigned a1f[2][4], a2f[2][4], b1f[4][2], b2f[4][2];
#pragma unroll
            for (int mt = 0; mt < 2; mt++) {
                int rbase = (wm * 32 + mt * 16 + g) * LDA + k + i2;
                load_afrag(a1f[mt], A1, rbase);
                load_afrag(a2f[mt], A2, rbase);
            }
#pragma unroll
            for (int q = 0; q < 4; q++) {
                int rb = (wn * 32 + q * 8 + g) * LDB + k + i2;
                b1f[q][0] = *(const unsigned*)(B1 + rb);
                b1f[q][1] = *(const unsigned*)(B1 + rb + 8);
                b2f[q][0] = *(const unsigned*)(B2 + rb);
                b2f[q][1] = *(const unsigned*)(B2 + rb + 8);
            }
#pragma unroll
            for (int mt = 0; mt < 2; mt++)
#pragma unroll
                for (int q = 0; q < 4; q++) {
                    mma16816(acc[mt][q], a1f[mt], b1f[q][0], b1f[q][1]);
                    mma16816(acc[mt][q], a1f[mt], b2f[q][0], b2f[q][1]);
                    mma16816(acc[mt][q], a2f[mt], b1f[q][0], b1f[q][1]);
                }
        }
        __syncthreads();               // all reads of stage kc done before next overwrite cycle
    }

    __half* o1 = g_h1[pin ^ 1];
    __half* o2 = g_h2[pin ^ 1];
    const int jb = j0 + wn * 8 + i2;
#pragma unroll
    for (int mt = 0; mt < 2; mt++)
#pragma unroll
        for (int rs = 0; rs < 2; rs++) {
            int r = wm * 32 + mt * 16 + g + rs * 8;
            int sb = sb0 + r;
            int tok = toks[r];
            float2 gv[4];
#pragma unroll
            for (int q = 0; q < 4; q++) {
                int n = q * Hz + jb;
                float2 e = *(const float2*)&E[(size_t)tok * G4z + n];
                gv[q] = make_float2(acc[mt][q][rs * 2 + 0] + e.x,
                                    acc[mt][q][rs * 2 + 1] + e.y);
            }
            int idx = sb * Hz + jb;
            float2 cold = *(const float2*)&g_c[idx];
            float cn0 = sigm(gv[1].x) * cold.x + sigm(gv[0].x) * tanhf(gv[2].x);
            float cn1 = sigm(gv[1].y) * cold.y + sigm(gv[0].y) * tanhf(gv[2].y);
            float hn0 = sigm(gv[3].x) * tanhf(cn0);
            float hn1 = sigm(gv[3].y) * tanhf(cn1);
            *(float2*)&g_c[idx] = make_float2(cn0, cn1);
            __half p0 = __float2half_rn(hn0), p1 = __float2half_rn(hn1);
            __half q0 = __float2half_rn(hn0 - __half2float(p0));
            __half q1 = __float2half_rn(hn1 - __half2float(p1));
            *(__half2*)&o1[idx] = __halves2half2(p0, p1);
            *(__half2*)&o2[idx] = __halves2half2(q0, q1);
        }
#undef A2_ST
#undef B2_ST
}

// ---------------- output head ----------------
__global__ __launch_bounds__(256) void k_outheadh(const float* __restrict__ bout,
                                                  float* __restrict__ out) {
    __half* A1 = smh;
    __half* A2 = smh + 64 * LDA;
    __half* B1 = smh + 2 * 64 * LDA;
    __half* B2 = smh + 2 * 64 * LDA + 64 * LDB;
    const int tid = threadIdx.x;
    const int m0 = blockIdx.x * 64;
    const int lane = tid & 31, warp = tid >> 5;
    const int wm = warp >> 2, wn = warp & 3;
    const int g = lane >> 2, i2 = (lane & 3) * 2;
    float acc[2][2][4] = {};

    for (int kc = 0; kc < 8; kc++) {
        int k0 = kc * 64;
        __syncthreads();
#pragma unroll
        for (int it = 0; it < 2; it++) {
            int c = tid + it * 256, r = c >> 3, col = (c & 7) * 8;
            *(uint4*)(A1 + r * LDA + col) = *(const uint4*)(g_hs1 + (size_t)(m0 + r) * Hz + k0 + col);
            *(uint4*)(A2 + r * LDA + col) = *(const uint4*)(g_hs2 + (size_t)(m0 + r) * Hz + k0 + col);
            *(uint4*)(B1 + r * LDB + col) = *(const uint4*)(g_Wo1 + (size_t)r * Hz + k0 + col);
            *(uint4*)(B2 + r * LDB + col) = *(const uint4*)(g_Wo2 + (size_t)r * Hz + k0 + col);
        }
        __syncthreads();
#pragma unroll
        for (int kk = 0; kk < 4; kk++) {
            int k = kk * 16;
            unsigned a1f[2][4], a2f[2][4], b1f[2][2], b2f[2][2];
#pragma unroll
            for (int mt = 0; mt < 2; mt++) {
                int rbase = (wm * 32 + mt * 16 + g) * LDA + k + i2;
                load_afrag(a1f[mt], A1, rbase);
                load_afrag(a2f[mt], A2, rbase);
            }
#pragma unroll
            for (int nt = 0; nt < 2; nt++) {
                int rb = (wn * 16 + nt * 8 + g) * LDB + k + i2;
                b1f[nt][0] = *(const unsigned*)(B1 + rb);
                b1f[nt][1] = *(const unsigned*)(B1 + rb + 8);
                b2f[nt][0] = *(const unsigned*)(B2 + rb);
                b2f[nt][1] = *(const unsigned*)(B2 + rb + 8);
            }
#pragma unroll
            for (int mt = 0; mt < 2; mt++)
#pragma unroll
                for (int nt = 0; nt < 2; nt++) {
                    mma16816(acc[mt][nt], a1f[mt], b1f[nt][0], b1f[nt][1]);
                    mma16816(acc[mt][nt], a1f[mt], b2f[nt][0], b2f[nt][1]);
                    mma16816(acc[mt][nt], a2f[mt], b1f[nt][0], b1f[nt][1]);
                }
        }
    }
#pragma unroll
    for (int mt = 0; mt < 2; mt++)
#pragma unroll
        for (int rs = 0; rs < 2; rs++)
#pragma unroll
            for (int jj = 0; jj < 2; jj++) {
                int m = m0 + wm * 32 + mt * 16 + g + rs * 8;
                int b = m & (Bz - 1), tt = m >> 9;
                int ci = rs * 2 + jj;
#pragma unroll
                for (int nt = 0; nt < 2; nt++) {
                    int v = wn * 16 + nt * 8 + i2 + jj;
                    out[((size_t)b * Tz + tt) * Vz + v] = acc[mt][nt][ci] + bout[v];
                }
            }
}

// ---------------- launch ----------------
extern "C" void kernel_launch(void* const* d_in, const int* in_sizes, int n_in,
                              void* d_out, int out_size) {
    const int* x   = (const int*)d_in[0];
    const int* tgt = (const int*)d_in[1];
    const float* eps   = (const float*)d_in[2];
    const float* emb   = (const float*)d_in[3];
    const float* Wih_f = (const float*)d_in[4];
    const float* Whh_f = (const float*)d_in[5];
    const float* b_f   = (const float*)d_in[6];
    const float* Wih_b = (const float*)d_in[7];
    const float* Whh_b = (const float*)d_in[8];
    const float* b_b   = (const float*)d_in[9];
    const float* W_mu  = (const float*)d_in[10];
    const float* b_mu  = (const float*)d_in[11];
    const float* W_lv  = (const float*)d_in[12];
    const float* b_lv  = (const float*)d_in[13];
    const float* W_di  = (const float*)d_in[14];
    const float* b_di  = (const float*)d_in[15];
    const float* Wih_d = (const float*)d_in[16];
    const float* Whh_d = (const float*)d_in[17];
    const float* b_d   = (const float*)d_in[18];
    const float* W_out = (const float*)d_in[19];
    const float* b_out = (const float*)d_in[20];

    float* out  = (float*)d_out;
    float* mu_o = out + (size_t)Bz * Tz * Vz;
    float* lv_o = mu_o + Bz * Lz;

    cudaFuncSetAttribute(k_steph,    cudaFuncAttributeMaxDynamicSharedMemorySize, SMEM_STEP);
    cudaFuncSetAttribute(k_steph2,   cudaFuncAttributeMaxDynamicSharedMemorySize, SMEM_STEP2);
    cudaFuncSetAttribute(k_outheadh, cudaFuncAttributeMaxDynamicSharedMemorySize, SMEM_OUT);

    __half *uf1, *uf2, *ub1, *ub2, *ud1, *ud2, *wo1, *wo2;
    float *ef, *eb, *ed, *hcat, *z, *zp, *htmp;
    cudaGetSymbolAddress((void**)&uf1, g_Uf1); cudaGetSymbolAddress((void**)&uf2, g_Uf2);
    cudaGetSymbolAddress((void**)&ub1, g_Ub1); cudaGetSymbolAddress((void**)&ub2, g_Ub2);
    cudaGetSymbolAddress((void**)&ud1, g_Ud1); cudaGetSymbolAddress((void**)&ud2, g_Ud2);
    cudaGetSymbolAddress((void**)&wo1, g_Wo1); cudaGetSymbolAddress((void**)&wo2, g_Wo2);
    cudaGetSymbolAddress((void**)&ef, g_EF);   cudaGetSymbolAddress((void**)&eb, g_EB);
    cudaGetSymbolAddress((void**)&ed, g_ED);
    cudaGetSymbolAddress((void**)&hcat, g_hcat);
    cudaGetSymbolAddress((void**)&z, g_z);
    cudaGetSymbolAddress((void**)&zp, g_zp);
    cudaGetSymbolAddress((void**)&htmp, g_htmp);

    k_split<<<512, 256>>>(Whh_f, uf1, uf2, G4z * Hz);
    k_split<<<512, 256>>>(Whh_b, ub1, ub2, G4z * Hz);
    k_split<<<512, 256>>>(Whh_d, ud1, ud2, G4z * Hz);
    k_split<<<64, 256>>>(W_out, wo1, wo2, Vz * Hz);

    k_gemm<<<dim3(32, 1), 256>>>(Ez, emb, Ez, Wih_f, Ez, b_f, ef, G4z);
    k_gemm<<<dim3(32, 1), 256>>>(Ez, emb, Ez, Wih_b, Ez, b_b, eb, G4z);
    k_gemm<<<dim3(32, 1), 256>>>(Ez, emb, Ez, Wih_d, ELz, b_d, ed, G4z);

    dim3 encGrid(Hz / 32, 8);    // (16, 8): 128 CTAs, both dirs, 1 wave
    dim3 decGrid(Hz / 32, 8);    // (16, 8): 128 CTAs
    int zeroBlocks2 = (2 * Bz * Hz + 255) / 256;
    int zeroBlocks1 = (Bz * Hz + 255) / 256;

    // ---- encoder (both directions, BM=128, single wave) ----
    k_zero_state<<<zeroBlocks2, 256>>>();
    for (int t = 0; t < Tz; t++)
        k_steph2<<<encGrid, 512, SMEM_STEP2>>>(t, t & 1, uf1, uf2, ub1, ub2, x, ef, eb);
    k_copy_hcat<<<zeroBlocks2, 256>>>();

    // ---- latent heads + reparameterize ----
    k_gemm<<<dim3(Lz / 64, Bz / 64), 256>>>(2 * Hz, hcat, 2 * Hz, W_mu, 2 * Hz, b_mu, mu_o, Lz);
    k_gemm<<<dim3(Lz / 64, Bz / 64), 256>>>(2 * Hz, hcat, 2 * Hz, W_lv, 2 * Hz, b_lv, lv_o, Lz);
    k_reparam<<<(Bz * Lz + 255) / 256, 256>>>(eps, mu_o, lv_o);

    // ---- decoder prologue ----
    k_gemm<<<dim3(G4z / 64, Bz / 64), 256>>>(Lz, z, Lz, Wih_d + Ez, ELz, nullptr, zp, G4z);
    k_gemm<<<dim3(Hz / 64, Bz / 64), 256>>>(Lz, z, Lz, W_di, Lz, b_di, htmp, Hz);
    k_hd_init<<<zeroBlocks1, 256>>>();

    // ---- decoder recurrence ----
    for (int t = 0; t < Tz; t++)
        k_steph<<<decGrid, 512, SMEM_STEP>>>(t, t & 1, ud1, ud2, tgt, ed, 1, 1);

    // ---- output head ----
    k_outheadh<<<(Tz * Bz) / 64, 256, SMEM_OUT>>>(b_out, out);
}